// round 8
// baseline (speedup 1.0000x reference)
#include <cuda_runtime.h>
#include <cuda_bf16.h>
#include <math.h>
#include <cstdint>

// Problem constants
#define BATCH 4
#define SEQ   2048
#define DIM   1024
#define HEADS 16
#define DH    64
#define NF    64
#define NBH   (BATCH*HEADS)          // 64
#define ROWS  (NBH*SEQ)              // 131072 head-rows
#define MROWS (BATCH*SEQ)            // 8192 GEMM rows
#define CH    64                     // chunk length
#define NCHUNK (SEQ/CH)              // 32
#define PAD   68

// ---------------- device scratch ----------------
__device__ float g_Q[ROWS*DH];
__device__ float g_K[ROWS*DH];
__device__ float g_V[ROWS*DH];
__device__ float g_phiq[ROWS*NF];
__device__ float g_phik[ROWS*NF];
__device__ float g_kv[NBH*NCHUNK*NF*DH];
__device__ float g_ks[NBH*NCHUNK*NF];
// bf16 split buffers
__device__ __nv_bfloat16 g_xhi[MROWS*DIM];
__device__ __nv_bfloat16 g_xlo[MROWS*DIM];
__device__ __nv_bfloat16 g_ahi[MROWS*DIM];
__device__ __nv_bfloat16 g_alo[MROWS*DIM];
__device__ __nv_bfloat16 g_whi[4*DIM*DIM];
__device__ __nv_bfloat16 g_wlo[4*DIM*DIM];

// ================= helpers =================
__device__ __forceinline__ uint32_t smem_u32(const void* p) {
    uint32_t a;
    asm("{ .reg .u64 tmp; cvta.to.shared.u64 tmp, %1; cvt.u32.u64 %0, tmp; }" : "=r"(a) : "l"(p));
    return a;
}
__device__ __forceinline__ void ldm_x4(uint32_t* r, uint32_t addr) {
    asm volatile("ldmatrix.sync.aligned.m8n8.x4.shared.b16 {%0,%1,%2,%3}, [%4];"
        : "=r"(r[0]), "=r"(r[1]), "=r"(r[2]), "=r"(r[3]) : "r"(addr));
}
__device__ __forceinline__ void mma_bf16(float* d, const uint32_t* a, const uint32_t* b) {
    asm volatile("mma.sync.aligned.m16n8k16.row.col.f32.bf16.bf16.f32 "
        "{%0,%1,%2,%3}, {%4,%5,%6,%7}, {%8,%9}, {%0,%1,%2,%3};"
        : "+f"(d[0]), "+f"(d[1]), "+f"(d[2]), "+f"(d[3])
        : "r"(a[0]), "r"(a[1]), "r"(a[2]), "r"(a[3]), "r"(b[0]), "r"(b[1]));
}
__device__ __forceinline__ void cp16(uint32_t dst, const void* src) {
    asm volatile("cp.async.cg.shared.global [%0], [%1], 16;" :: "r"(dst), "l"(src));
}
#define CP_COMMIT() asm volatile("cp.async.commit_group;" ::: "memory")
#define CP_WAIT(N)  asm volatile("cp.async.wait_group %0;" :: "n"(N) : "memory")

// ================= fused split conversion =================
__global__ __launch_bounds__(256) void convert_all(
    const float* __restrict__ x,
    const float* __restrict__ Wq, const float* __restrict__ Wk,
    const float* __restrict__ Wv, const float* __restrict__ Wout,
    __nv_bfloat16* __restrict__ xhi, __nv_bfloat16* __restrict__ xlo,
    __nv_bfloat16* __restrict__ whi, __nv_bfloat16* __restrict__ wlo)
{
    const int b = blockIdx.x;
    const float* src;
    __nv_bfloat16 *hi, *lo;
    int i;
    if (b < 8192) {
        src = x; hi = xhi; lo = xlo;
        i = b * 256 + threadIdx.x;
    } else {
        const int wb = b - 8192;
        const int w = wb >> 10;
        const int r = wb & 1023;
        src = (w == 0) ? Wq : (w == 1) ? Wk : (w == 2) ? Wv : Wout;
        hi = whi + (size_t)w * DIM * DIM;
        lo = wlo + (size_t)w * DIM * DIM;
        i = r * 256 + threadIdx.x;
    }
    float4 v = ((const float4*)src)[i];
    __nv_bfloat16 h0 = __float2bfloat16(v.x);
    __nv_bfloat16 h1 = __float2bfloat16(v.y);
    __nv_bfloat16 h2 = __float2bfloat16(v.z);
    __nv_bfloat16 h3 = __float2bfloat16(v.w);
    __nv_bfloat16 l0 = __float2bfloat16(v.x - __bfloat162float(h0));
    __nv_bfloat16 l1 = __float2bfloat16(v.y - __bfloat162float(h1));
    __nv_bfloat16 l2 = __float2bfloat16(v.z - __bfloat162float(h2));
    __nv_bfloat16 l3 = __float2bfloat16(v.w - __bfloat162float(h3));
    __nv_bfloat162 p;
    p.x = h0; p.y = h1; ((__nv_bfloat162*)hi)[2*i]   = p;
    p.x = h2; p.y = h3; ((__nv_bfloat162*)hi)[2*i+1] = p;
    p.x = l0; p.y = l1; ((__nv_bfloat162*)lo)[2*i]   = p;
    p.x = l2; p.y = l3; ((__nv_bfloat162*)lo)[2*i+1] = p;
}

// ================= HMMA split-bf16 GEMM: 256x128 tile, 3-stage cp.async =================
// C[M,N=1024] = A[M,K] @ B[N,K]^T, A=Ahi+Alo, B=Bhi+Blo (drop lo*lo), fp32 accum.
// 8 warps as 4m x 2n; warp tile 64x64; k-slab 32; 1 CTA/SM (128-reg acc).
#define A_TS (256*80)                  // 20480 B: 256x32 bf16 tile @ 80B row stride
#define B_TS (128*80)                  // 10240 B
#define BUFB (2*A_TS + 2*B_TS)         // 61440 B per stage
#define NSTAGE 3

__global__ __launch_bounds__(256, 1) void gemm_hmma_split(
    const __nv_bfloat16* __restrict__ Ahi, const __nv_bfloat16* __restrict__ Alo,
    const __nv_bfloat16* __restrict__ Bhi_all, const __nv_bfloat16* __restrict__ Blo_all,
    float* __restrict__ C0, float* __restrict__ C1, float* __restrict__ C2, int K)
{
    extern __shared__ char smx[];
    const int t = threadIdx.x;
    const int wid = t >> 5, lane = t & 31;
    const int wm = wid >> 1, wn = wid & 1;          // 4m x 2n
    const int bm = blockIdx.y * 256;
    const int which = blockIdx.x >> 3;
    const int bn = (blockIdx.x & 7) * 128;
    const __nv_bfloat16* Bh = Bhi_all + (size_t)which * DIM * DIM;
    const __nv_bfloat16* Bl = Blo_all + (size_t)which * DIM * DIM;
    float* C = (which == 0) ? C0 : (which == 1) ? C1 : C2;

    const uint32_t smb = smem_u32(smx);
    const __nv_bfloat16* srcs[4] = {Ahi, Alo, Bh, Bl};
    const uint32_t toff[4] = {0u, (uint32_t)A_TS, (uint32_t)(2*A_TS), (uint32_t)(2*A_TS + B_TS)};

    float acc[4][8][4];
#pragma unroll
    for (int i = 0; i < 4; i++)
#pragma unroll
        for (int j = 0; j < 8; j++)
#pragma unroll
            for (int q = 0; q < 4; q++) acc[i][j][q] = 0.f;

    // ---- cp.async one k-slab into stage b: 12 x 16B per thread ----
    auto issue = [&](int s, int b) {
        const int k0 = s * 32;
#pragma unroll
        for (int q = 0; q < 12; q++) {
            const int tile = (q < 4) ? 0 : (q < 8) ? 1 : (q < 10) ? 2 : 3;
            const int i = ((q < 8) ? (q & 3) : (q & 1)) * 256 + t;
            const int r = i >> 2, ch = i & 3;
            const int rb = (tile < 2) ? bm : bn;
            cp16(smb + b * BUFB + toff[tile] + r * 80 + ch * 16,
                 srcs[tile] + (size_t)(rb + r) * K + k0 + ch * 8);
        }
        CP_COMMIT();
    };

    // ---- compute one k-slab from stage b ----
    auto compute = [&](int b) {
        const uint32_t Ahb = smb + b * BUFB;
        const uint32_t Alb = Ahb + A_TS;
        const uint32_t Bhb = Ahb + 2 * A_TS;
        const uint32_t Blb = Bhb + B_TS;
        const int lrA = lane & 15, kbA = lane >> 4;
        const int nrB = (lane & 7) + ((lane >> 4) << 3);
        const int kbB = (lane >> 3) & 1;
#pragma unroll
        for (int ks = 0; ks < 2; ks++) {
            uint32_t bhf[8][2], blf[8][2];
#pragma unroll
            for (int np = 0; np < 4; np++) {
                uint32_t off = (uint32_t)((wn * 64 + np * 16 + nrB) * 80 + ks * 32 + kbB * 16);
                uint32_t tmp[4];
                ldm_x4(tmp, Bhb + off);
                bhf[2*np][0] = tmp[0]; bhf[2*np][1] = tmp[1];
                bhf[2*np+1][0] = tmp[2]; bhf[2*np+1][1] = tmp[3];
                ldm_x4(tmp, Blb + off);
                blf[2*np][0] = tmp[0]; blf[2*np][1] = tmp[1];
                blf[2*np+1][0] = tmp[2]; blf[2*np+1][1] = tmp[3];
            }
#pragma unroll
            for (int ma = 0; ma < 4; ma++) {
                uint32_t ah[4], al[4];
                uint32_t off = (uint32_t)((wm * 64 + ma * 16 + lrA) * 80 + ks * 32 + kbA * 16);
                ldm_x4(ah, Ahb + off);
                ldm_x4(al, Alb + off);
#pragma unroll
                for (int na = 0; na < 8; na++) {
                    mma_bf16(acc[ma][na], ah, bhf[na]);
                    mma_bf16(acc[ma][na], ah, blf[na]);
                    mma_bf16(acc[ma][na], al, bhf[na]);
                }
            }
        }
    };

    const int S = K / 32;
    issue(0, 0);
    issue(1, 1);
    for (int s = 0; s < S; s++) {
        if (s + 1 < S) { CP_WAIT(1); } else { CP_WAIT(0); }
        __syncthreads();
        if (s + 2 < S) issue(s + 2, (s + 2) % NSTAGE);
        compute(s % NSTAGE);
    }

    // ---- epilogue ----
    const int g = lane >> 2, tig = lane & 3;
#pragma unroll
    for (int ma = 0; ma < 4; ma++) {
        const int r0 = bm + wm * 64 + ma * 16 + g;
#pragma unroll
        for (int na = 0; na < 8; na++) {
            const int c = bn + wn * 64 + na * 8 + tig * 2;
            *(float2*)(C + (size_t)r0 * DIM + c)       = make_float2(acc[ma][na][0], acc[ma][na][1]);
            *(float2*)(C + (size_t)(r0 + 8) * DIM + c) = make_float2(acc[ma][na][2], acc[ma][na][3]);
        }
    }
}

// ================= fused feature map =================
__global__ __launch_bounds__(256) void feature_both(const float* __restrict__ Q,
                                                    const float* __restrict__ Kd,
                                                    const float* __restrict__ proj,
                                                    float* __restrict__ phiq,
                                                    float* __restrict__ phik)
{
    __shared__ float XsT[64*PAD];
    __shared__ float pT[64*PAD];
    const int t = threadIdx.x;
    const int nb = ROWS / 64;
    const int is_query = (blockIdx.x < nb) ? 1 : 0;
    const int blk = is_query ? blockIdx.x : blockIdx.x - nb;
    const float* X = is_query ? Q : Kd;
    float* phi = is_query ? phiq : phik;
    const size_t base = (size_t)blk * 64 * 64;

    for (int i = t; i < 4096; i += 256) { int f_ = i >> 6, d_ = i & 63; pT[d_*PAD + f_] = proj[i]; }
    for (int i = t; i < 4096; i += 256) { int r_ = i >> 6, d_ = i & 63; XsT[d_*PAD + r_] = X[base + i]; }
    __syncthreads();

    const int r0 = (t >> 4) << 2;
    const int f0 = (t & 15) << 2;
    float acc[4][4], sq[4];
#pragma unroll
    for (int i = 0; i < 4; i++) { sq[i] = 0.f;
#pragma unroll
        for (int j = 0; j < 4; j++) acc[i][j] = 0.f; }

#pragma unroll
    for (int d = 0; d < 64; d++) {
        float4 a = *(const float4*)&XsT[d*PAD + r0];
        float4 b = *(const float4*)&pT[d*PAD + f0];
        float av[4] = {a.x, a.y, a.z, a.w};
        float bv[4] = {b.x, b.y, b.z, b.w};
#pragma unroll
        for (int i = 0; i < 4; i++) {
            sq[i] += av[i] * av[i];
#pragma unroll
            for (int j = 0; j < 4; j++) acc[i][j] += av[i] * bv[j];
        }
    }
    const float dn = 0.35355339059327373f;
    float dd[4][4];
#pragma unroll
    for (int i = 0; i < 4; i++)
#pragma unroll
        for (int j = 0; j < 4; j++) dd[i][j] = dn * acc[i][j];

    if (is_query) {
#pragma unroll
        for (int i = 0; i < 4; i++) {
            float mx = fmaxf(fmaxf(dd[i][0], dd[i][1]), fmaxf(dd[i][2], dd[i][3]));
#pragma unroll
            for (int o = 8; o >= 1; o >>= 1) mx = fmaxf(mx, __shfl_xor_sync(0xffffffffu, mx, o));
#pragma unroll
            for (int j = 0; j < 4; j++) dd[i][j] -= mx;
        }
    }
#pragma unroll
    for (int i = 0; i < 4; i++) {
        const float diag = sq[i] * (1.0f / 128.0f);
        float4 o;
        o.x = 0.125f * (expf(dd[i][0] - diag) + 1e-4f);
        o.y = 0.125f * (expf(dd[i][1] - diag) + 1e-4f);
        o.z = 0.125f * (expf(dd[i][2] - diag) + 1e-4f);
        o.w = 0.125f * (expf(dd[i][3] - diag) + 1e-4f);
        *(float4*)&phi[((size_t)blk * 64 + r0 + i) * 64 + f0] = o;
    }
}

// ================= chunk_local =================
__global__ __launch_bounds__(256) void chunk_local_kernel(const float* __restrict__ phiK,
                                                          const float* __restrict__ V,
                                                          float* __restrict__ kvloc,
                                                          float* __restrict__ kloc)
{
    __shared__ float ks[64*PAD];
    __shared__ float vs[64*PAD];
    const int t = threadIdx.x;
    const int chunk = blockIdx.x, bh = blockIdx.y;
    const size_t base = ((size_t)bh * SEQ + chunk * CH) * 64;

    for (int i = t; i < 1024; i += 256) {
        int r = i >> 4, c4 = (i & 15) << 2;
        *(float4*)&ks[r*PAD + c4] = *(const float4*)(phiK + base + (size_t)r*64 + c4);
        *(float4*)&vs[r*PAD + c4] = *(const float4*)(V    + base + (size_t)r*64 + c4);
    }
    __syncthreads();

    const int f0 = (t >> 4) << 2;
    const int c0 = (t & 15) << 2;
    float acc[4][4], kl[4];
#pragma unroll
    for (int i = 0; i < 4; i++) { kl[i] = 0.f;
#pragma unroll
        for (int j = 0; j < 4; j++) acc[i][j] = 0.f; }

#pragma unroll 8
    for (int r = 0; r < 64; r++) {
        float4 k4 = *(const float4*)&ks[r*PAD + f0];
        float4 v4 = *(const float4*)&vs[r*PAD + c0];
        float kv[4] = {k4.x, k4.y, k4.z, k4.w};
        float vv[4] = {v4.x, v4.y, v4.z, v4.w};
#pragma unroll
        for (int i = 0; i < 4; i++) {
            kl[i] += kv[i];
#pragma unroll
            for (int j = 0; j < 4; j++) acc[i][j] += kv[i] * vv[j];
        }
    }
    const size_t ob = ((size_t)bh * NCHUNK + chunk) * (64*64);
#pragma unroll
    for (int i = 0; i < 4; i++)
        *(float4*)&kvloc[ob + (size_t)(f0+i)*64 + c0] =
            make_float4(acc[i][0], acc[i][1], acc[i][2], acc[i][3]);
    if ((t & 15) == 0) {
        const size_t kb = ((size_t)bh * NCHUNK + chunk) * 64 + f0;
#pragma unroll
        for (int i = 0; i < 4; i++) kloc[kb + i] = kl[i];
    }
}

// ================= prefix =================
__global__ __launch_bounds__(256) void prefix_kernel(float* __restrict__ kvloc,
                                                     float* __restrict__ kloc)
{
    const int g = blockIdx.x, bh = blockIdx.y;
    const int t = threadIdx.x;
    const int e = g * 256 + t;
    float run = 0.f;
    for (int c = 0; c < NCHUNK; c++) {
        const size_t idx = ((size_t)bh * NCHUNK + c) * 4096 + e;
        float v = kvloc[idx];
        kvloc[idx] = run;
        run += v;
    }
    if (g == 0 && t < 64) {
        float rk = 0.f;
        for (int c = 0; c < NCHUNK; c++) {
            const size_t b = ((size_t)bh * NCHUNK + c) * 64 + t;
            float v = kloc[b];
            kloc[b] = rk;
            rk += v;
        }
    }
}

// ================= chunk_out =================
__global__ __launch_bounds__(256) void chunk_out_kernel(const float* __restrict__ phiQ,
                                                        const float* __restrict__ phiK,
                                                        const float* __restrict__ Vg,
                                                        const float* __restrict__ KVp,
                                                        const float* __restrict__ Kp,
                                                        const float* __restrict__ Wpost,
                                                        __nv_bfloat16* __restrict__ ahi,
                                                        __nv_bfloat16* __restrict__ alo)
{
    extern __shared__ float sm[];
    float* QsT = sm;
    float* KsT = QsT + 64*PAD;
    float* Vs  = KsT + 64*PAD;
    float* KVs = Vs  + 64*PAD;
    float* Ss  = KVs + 64*PAD;
    float* Wps = Ss  + 64*PAD;
    float* den = Wps + 64*PAD;
    float* kps = den + 64;

    const int t = threadIdx.x;
    const int chunk = blockIdx.x, bh = blockIdx.y;
    const size_t base   = ((size_t)bh * SEQ + chunk * CH) * 64;
    const size_t kvbase = ((size_t)bh * NCHUNK + chunk) * 4096;

    for (int i = t; i < 1024; i += 256) {
        int r = i >> 4, c4 = (i & 15) << 2;
        float4 q = *(const float4*)(phiQ + base + (size_t)r*64 + c4);
        float4 k = *(const float4*)(phiK + base + (size_t)r*64 + c4);
        float4 w = *(const float4*)(Wpost + (size_t)r*64 + c4);   // r=e, c4=c
        QsT[(c4+0)*PAD + r] = q.x; QsT[(c4+1)*PAD + r] = q.y;
        QsT[(c4+2)*PAD + r] = q.z; QsT[(c4+3)*PAD + r] = q.w;
        KsT[(c4+0)*PAD + r] = k.x; KsT[(c4+1)*PAD + r] = k.y;
        KsT[(c4+2)*PAD + r] = k.z; KsT[(c4+3)*PAD + r] = k.w;
        Wps[(c4+0)*PAD + r] = w.x; Wps[(c4+1)*PAD + r] = w.y;
        Wps[(c4+2)*PAD + r] = w.z; Wps[(c4+3)*PAD + r] = w.w;
        *(float4*)&Vs [r*PAD + c4] = *(const float4*)(Vg  + base   + (size_t)r*64 + c4);
        *(float4*)&KVs[r*PAD + c4] = *(const float4*)(KVp + kvbase + (size_t)r*64 + c4);
    }
    if (t < 64) kps[t] = Kp[((size_t)bh * NCHUNK + chunk) * 64 + t];
    __syncthreads();

    const int r0 = (t >> 4) << 2;
    const int c0 = (t & 15) << 2;

    // ---- Phase S: S = Q K^T (+ kq = q . kprev) ----
    float sacc[4][4], kq[4];
#pragma unroll
    for (int i = 0; i < 4; i++) { kq[i] = 0.f;
#pragma unroll
        for (int j = 0; j < 4; j++) sacc[i][j] = 0.f; }
#pragma unroll 8
    for (int d = 0; d < 64; d++) {
        float4 q4 = *(const float4*)&QsT[d*PAD + r0];
        float4 k4 = *(const float4*)&KsT[d*PAD + c0];
        float kp = kps[d];
        float qv[4] = {q4.x, q4.y, q4.z, q4.w};
        float kv[4] = {k4.x, k4.y, k4.z, k4.w};
#pragma unroll
        for (int i = 0; i < 4; i++) {
            kq[i] += qv[i] * kp;
#pragma unroll
            for (int j = 0; j < 4; j++) sacc[i][j] += qv[i] * kv[j];
        }
    }
    float rs[4];
#pragma unroll
    for (int i = 0; i < 4; i++) {
        const int r = r0 + i;
        float m0 = (c0+0 <= r) ? sacc[i][0] : 0.f;
        float m1 = (c0+1 <= r) ? sacc[i][1] : 0.f;
        float m2 = (c0+2 <= r) ? sacc[i][2] : 0.f;
        float m3 = (c0+3 <= r) ? sacc[i][3] : 0.f;
        *(float4*)&Ss[r*PAD + c0] = make_float4(m0, m1, m2, m3);
        rs[i] = m0 + m1 + m2 + m3;
    }
#pragma unroll
    for (int o = 8; o >= 1; o >>= 1)
#pragma unroll
        for (int i = 0; i < 4; i++) rs[i] += __shfl_xor_sync(0xffffffffu, rs[i], o);
    if ((t & 15) == 0) {
#pragma unroll
        for (int i = 0; i < 4; i++) den[r0 + i] = fmaxf(rs[i] + kq[i], 1e-6f);
    }
    __syncthreads();

    // ---- Phase O: O = S V + Q KVprev ----
    float oacc[4][4];
#pragma unroll
    for (int i = 0; i < 4; i++)
#pragma unroll
        for (int j = 0; j < 4; j++) oacc[i][j] = 0.f;
#pragma unroll 4
    for (int j0 = 0; j0 < 64; j0 += 4) {
        float4 s4[4], v4[4];
#pragma unroll
        for (int i = 0; i < 4; i++)  s4[i]  = *(const float4*)&Ss[(r0+i)*PAD + j0];
#pragma unroll
        for (int jj = 0; jj < 4; jj++) v4[jj] = *(const float4*)&Vs[(j0+jj)*PAD + c0];
#pragma unroll
        for (int i = 0; i < 4; i++) {
            float sv[4] = {s4[i].x, s4[i].y, s4[i].z, s4[i].w};
#pragma unroll
            for (int jj = 0; jj < 4; jj++) {
                oacc[i][0] += sv[jj] * (&v4[jj].x)[0];
                oacc[i][1] += sv[jj] * (&v4[jj].x)[1];
                oacc[i][2] += sv[jj] * (&v4[jj].x)[2];
                oacc[i][3] += sv[jj] * (&v4[jj].x)[3];
            }
        }
    }
#pragma unroll 4
    for (int f0 = 0; f0 < 64; f0 += 4) {
        float4 q4[4], kv4[4];
#pragma unroll
        for (int jj = 0; jj < 4; jj++) {
            q4[jj]  = *(const float4*)&QsT[(f0+jj)*PAD + r0];
            kv4[jj] = *(const float4*)&KVs[(f0+jj)*PAD + c0];
        }
#pragma unroll
        for (int jj = 0; jj < 4; jj++) {
            float qv[4] = {q4[jj].x, q4[jj].y, q4[jj].z, q4[jj].w};
#pragma unroll
            for (int i = 0; i < 4; i++) {
                oacc[i][0] += qv[i] * (&kv4[jj].x)[0];
                oacc[i][1] += qv[i] * (&kv4[jj].x)[1];
                oacc[i][2] += qv[i] * (&kv4[jj].x)[2];
                oacc[i][3] += qv[i] * (&kv4[jj].x)[3];
            }
        }
    }
#pragma unroll
    for (int i = 0; i < 4; i++) {
        const float inv = 1.0f / den[r0 + i];
#pragma unroll
        for (int j = 0; j < 4; j++) oacc[i][j] *= inv;
    }
    __syncthreads();
#pragma unroll
    for (int i = 0; i < 4; i++)
        *(float4*)&Ss[(r0+i)*PAD + c0] = make_float4(oacc[i][0], oacc[i][1], oacc[i][2], oacc[i][3]);
    __syncthreads();

    // ---- Phase W: F = O @ Wpost^T ----
    float facc[4][4];
#pragma unroll
    for (int i = 0; i < 4; i++)
#pragma unroll
        for (int j = 0; j < 4; j++) facc[i][j] = 0.f;
#pragma unroll 4
    for (int cg = 0; cg < 64; cg += 4) {
        float4 o4[4], w4[4];
#pragma unroll
        for (int i = 0; i < 4; i++)   o4[i]  = *(const float4*)&Ss[(r0+i)*PAD + cg];
#pragma unroll
        for (int jj = 0; jj < 4; jj++) w4[jj] = *(const float4*)&Wps[(cg+jj)*PAD + c0];
#pragma unroll
        for (int i = 0; i < 4; i++) {
            float ov[4] = {o4[i].x, o4[i].y, o4[i].z, o4[i].w};
#pragma unroll
            for (int jj = 0; jj < 4; jj++) {
                facc[i][0] += ov[jj] * (&w4[jj].x)[0];
                facc[i][1] += ov[jj] * (&w4[jj].x)[1];
                facc[i][2] += ov[jj] * (&w4[jj].x)[2];
                facc[i][3] += ov[jj] * (&w4[jj].x)[3];
            }
        }
    }

    const int bi = bh >> 4, hi2 = bh & 15;
#pragma unroll
    for (int i = 0; i < 4; i++) {
        const int si = chunk * CH + r0 + i;
        const size_t ob = ((size_t)bi * SEQ + si) * DIM + hi2 * 64 + c0;
        __nv_bfloat162 hp[2], lp[2];
#pragma unroll
        for (int j = 0; j < 2; j++) {
            float fa = facc[i][2*j], fb = facc[i][2*j+1];
            __nv_bfloat16 ha = __float2bfloat16(fa);
            __nv_bfloat16 hb = __float2bfloat16(fb);
            hp[j].x = ha; hp[j].y = hb;
            lp[j].x = __float2bfloat16(fa - __bfloat162float(ha));
            lp[j].y = __float2bfloat16(fb - __bfloat162float(hb));
        }
        *(float2*)(ahi + ob) = *(float2*)hp;
        *(float2*)(alo + ob) = *(float2*)lp;
    }
}

// ================= launch =================
extern "C" void kernel_launch(void* const* d_in, const int* in_sizes, int n_in,
                              void* d_out, int out_size)
{
    const float* x     = (const float*)d_in[0];
    const float* Wq    = (const float*)d_in[1];
    const float* Wk    = (const float*)d_in[2];
    const float* Wv    = (const float*)d_in[3];
    const float* proj  = (const float*)d_in[4];
    const float* Wpost = (const float*)d_in[5];
    const float* Wout  = (const float*)d_in[6];
    float* out = (float*)d_out;

    float *pQ, *pK, *pV, *pphiq, *pphik, *pkv, *pks;
    __nv_bfloat16 *pxhi, *pxlo, *pahi, *palo, *pwhi, *pwlo;
    cudaGetSymbolAddress((void**)&pQ, g_Q);
    cudaGetSymbolAddress((void**)&pK, g_K);
    cudaGetSymbolAddress((void**)&pV, g_V);
    cudaGetSymbolAddress((void**)&pphiq, g_phiq);
    cudaGetSymbolAddress((void**)&pphik, g_phik);
    cudaGetSymbolAddress((void**)&pkv, g_kv);
    cudaGetSymbolAddress((void**)&pks, g_ks);
    cudaGetSymbolAddress((void**)&pxhi, g_xhi);
    cudaGetSymbolAddress((void**)&pxlo, g_xlo);
    cudaGetSymbolAddress((void**)&pahi, g_ahi);
    cudaGetSymbolAddress((void**)&palo, g_alo);
    cudaGetSymbolAddress((void**)&pwhi, g_whi);
    cudaGetSymbolAddress((void**)&pwlo, g_wlo);

    static const size_t chunk_smem = (size_t)(6*64*PAD + 128) * sizeof(float);
    cudaFuncSetAttribute(chunk_out_kernel, cudaFuncAttributeMaxDynamicSharedMemorySize,
                         (int)chunk_smem);
    static const int gemm_smem = NSTAGE * BUFB;     // 184320 B
    cudaFuncSetAttribute(gemm_hmma_split, cudaFuncAttributeMaxDynamicSharedMemorySize, gemm_smem);

    convert_all<<<12288, 256>>>(x, Wq, Wk, Wv, Wout, pxhi, pxlo, pwhi, pwlo);

    dim3 gqkv(24, MROWS/256);        // (24, 32): 3 weight groups x 8 n-tiles, 32 m-tiles
    gemm_hmma_split<<<gqkv, 256, gemm_smem>>>(pxhi, pxlo, pwhi, pwlo, pQ, pK, pV, DIM);

    feature_both<<<2*(ROWS/64), 256>>>(pQ, pK, proj, pphiq, pphik);

    dim3 gc(NCHUNK, NBH);
    chunk_local_kernel<<<gc, 256>>>(pphik, pV, pkv, pks);
    dim3 gp(16, NBH);
    prefix_kernel<<<gp, 256>>>(pkv, pks);
    chunk_out_kernel<<<gc, 256, chunk_smem>>>(pphiq, pphik, pV, pkv, pks, Wpost, pahi, palo);

    dim3 gout(8, MROWS/256);
    gemm_hmma_split<<<gout, 256, gemm_smem>>>(pahi, palo, pwhi + 3*DIM*DIM, pwlo + 3*DIM*DIM,
                                              out, out, out, DIM);
}

// round 10
// speedup vs baseline: 1.2919x; 1.2919x over previous
#include <cuda_runtime.h>
#include <cuda_fp16.h>
#include <math.h>
#include <cstdint>

// Problem constants
#define BATCH 4
#define SEQ   2048
#define DIM   1024
#define HEADS 16
#define DH    64
#define NF    64
#define NBH   (BATCH*HEADS)          // 64
#define ROWS  (NBH*SEQ)              // 131072 head-rows
#define MROWS (BATCH*SEQ)            // 8192 GEMM rows
#define CH    64                     // chunk length
#define NCHUNK (SEQ/CH)              // 32
#define PAD   68

// ---------------- device scratch ----------------
__device__ float g_Q[ROWS*DH];
__device__ float g_K[ROWS*DH];
__device__ float g_V[ROWS*DH];
__device__ float g_phiq[ROWS*NF];
__device__ float g_phik[ROWS*NF];
__device__ float g_kv[NBH*NCHUNK*NF*DH];
__device__ float g_ks[NBH*NCHUNK*NF];
// fp16 split buffers (A-side split, B single)
__device__ __half g_xhi[MROWS*DIM];
__device__ __half g_xlo[MROWS*DIM];
__device__ __half g_ahi[MROWS*DIM];
__device__ __half g_alo[MROWS*DIM];
__device__ __half g_wh[4*DIM*DIM];

// ================= helpers =================
__device__ __forceinline__ uint32_t smem_u32(const void* p) {
    uint32_t a;
    asm("{ .reg .u64 tmp; cvta.to.shared.u64 tmp, %1; cvt.u32.u64 %0, tmp; }" : "=r"(a) : "l"(p));
    return a;
}
__device__ __forceinline__ void ldm_x4(uint32_t* r, uint32_t addr) {
    asm volatile("ldmatrix.sync.aligned.m8n8.x4.shared.b16 {%0,%1,%2,%3}, [%4];"
        : "=r"(r[0]), "=r"(r[1]), "=r"(r[2]), "=r"(r[3]) : "r"(addr));
}
__device__ __forceinline__ void mma_f16(float* d, const uint32_t* a, const uint32_t* b) {
    asm volatile("mma.sync.aligned.m16n8k16.row.col.f32.f16.f16.f32 "
        "{%0,%1,%2,%3}, {%4,%5,%6,%7}, {%8,%9}, {%0,%1,%2,%3};"
        : "+f"(d[0]), "+f"(d[1]), "+f"(d[2]), "+f"(d[3])
        : "r"(a[0]), "r"(a[1]), "r"(a[2]), "r"(a[3]), "r"(b[0]), "r"(b[1]));
}
__device__ __forceinline__ void cp16(uint32_t dst, const void* src) {
    asm volatile("cp.async.cg.shared.global [%0], [%1], 16;" :: "r"(dst), "l"(src));
}
#define CP_COMMIT() asm volatile("cp.async.commit_group;" ::: "memory")
#define CP_WAIT(N)  asm volatile("cp.async.wait_group %0;" :: "n"(N) : "memory")

// ================= fused conversion: x -> fp16 split, weights -> fp16 =================
__global__ __launch_bounds__(256) void convert_all(
    const float* __restrict__ x,
    const float* __restrict__ Wq, const float* __restrict__ Wk,
    const float* __restrict__ Wv, const float* __restrict__ Wout,
    __half* __restrict__ xhi, __half* __restrict__ xlo,
    __half* __restrict__ wh)
{
    const int b = blockIdx.x;
    if (b < 8192) {
        const int i = b * 256 + threadIdx.x;
        float4 v = ((const float4*)x)[i];
        __half h0 = __float2half(v.x), h1 = __float2half(v.y);
        __half h2 = __float2half(v.z), h3 = __float2half(v.w);
        __half2 p;
        p.x = h0; p.y = h1; ((__half2*)xhi)[2*i]   = p;
        p.x = h2; p.y = h3; ((__half2*)xhi)[2*i+1] = p;
        p.x = __float2half(v.x - __half2float(h0));
        p.y = __float2half(v.y - __half2float(h1));
        ((__half2*)xlo)[2*i] = p;
        p.x = __float2half(v.z - __half2float(h2));
        p.y = __float2half(v.w - __half2float(h3));
        ((__half2*)xlo)[2*i+1] = p;
    } else {
        const int wb = b - 8192;
        const int w = wb >> 10;
        const int r = wb & 1023;
        const float* src = (w == 0) ? Wq : (w == 1) ? Wk : (w == 2) ? Wv : Wout;
        __half* hi = wh + (size_t)w * DIM * DIM;
        const int i = r * 256 + threadIdx.x;
        float4 v = ((const float4*)src)[i];
        __half2 p;
        p.x = __float2half(v.x); p.y = __float2half(v.y);
        ((__half2*)hi)[2*i] = p;
        p.x = __float2half(v.z); p.y = __float2half(v.w);
        ((__half2*)hi)[2*i+1] = p;
    }
}

// ================= HMMA fp16 A-split GEMM: 128x128 tile, 3-stage, 2 CTA/SM =================
// C[M,N=1024] = (Ah+Al)[M,K] @ B[N,K]^T, fp32 accum, B single fp16.
#define TS 10240                       // one 128x32 fp16 tile @ 80B row stride
#define BUFB (3*TS)                    // Ah, Al, Bh per stage (30720 B)
#define NSTAGE 3

__global__ __launch_bounds__(256, 2) void gemm_hmma_split(
    const __half* __restrict__ Ahi, const __half* __restrict__ Alo,
    const __half* __restrict__ Bh_all,
    float* __restrict__ C0, float* __restrict__ C1, float* __restrict__ C2, int K)
{
    extern __shared__ char smx[];
    const int t = threadIdx.x;
    const int wid = t >> 5, lane = t & 31;
    const int wm = wid >> 2, wn = wid & 3;          // 2m x 4n, warp tile 64x32
    const int bm = blockIdx.y * 128;
    const int which = blockIdx.x >> 3;
    const int bn = (blockIdx.x & 7) * 128;
    const __half* Bh = Bh_all + (size_t)which * DIM * DIM;
    float* C = (which == 0) ? C0 : (which == 1) ? C1 : C2;

    const uint32_t smb = smem_u32(smx);
    const __half* srcs[3] = {Ahi, Alo, Bh};

    float acc[4][4][4];
#pragma unroll
    for (int i = 0; i < 4; i++)
#pragma unroll
        for (int j = 0; j < 4; j++)
#pragma unroll
            for (int q = 0; q < 4; q++) acc[i][j][q] = 0.f;

    // ---- cp.async one k-slab into stage b: 6 x 16B per thread ----
    auto issue = [&](int s, int b) {
        const int k0 = s * 32;
#pragma unroll
        for (int q = 0; q < 6; q++) {
            const int tile = q >> 1;
            const int i = (q & 1) * 256 + t;        // 0..511
            const int r = i >> 2, ch = i & 3;
            const int rb = (tile < 2) ? bm : bn;
            cp16(smb + b * BUFB + tile * TS + r * 80 + ch * 16,
                 srcs[tile] + (size_t)(rb + r) * K + k0 + ch * 8);
        }
        CP_COMMIT();
    };

    // ---- compute one k-slab from stage b ----
    auto compute = [&](int b) {
        const uint32_t Ahb = smb + b * BUFB;
        const uint32_t Alb = Ahb + TS;
        const uint32_t Bhb = Ahb + 2 * TS;
        const int lrA = lane & 15, kbA = lane >> 4;
        const int nrB = (lane & 7) + ((lane >> 4) << 3);
        const int kbB = (lane >> 3) & 1;
#pragma unroll
        for (int ks = 0; ks < 2; ks++) {
            uint32_t bhf[4][2];
#pragma unroll
            for (int np = 0; np < 2; np++) {
                uint32_t off = (uint32_t)((wn * 32 + np * 16 + nrB) * 80 + ks * 32 + kbB * 16);
                uint32_t tmp[4];
                ldm_x4(tmp, Bhb + off);
                bhf[2*np][0] = tmp[0]; bhf[2*np][1] = tmp[1];
                bhf[2*np+1][0] = tmp[2]; bhf[2*np+1][1] = tmp[3];
            }
#pragma unroll
            for (int ma = 0; ma < 4; ma++) {
                uint32_t ah[4], al[4];
                uint32_t off = (uint32_t)((wm * 64 + ma * 16 + lrA) * 80 + ks * 32 + kbA * 16);
                ldm_x4(ah, Ahb + off);
                ldm_x4(al, Alb + off);
#pragma unroll
                for (int na = 0; na < 4; na++) {
                    mma_f16(acc[ma][na], ah, bhf[na]);
                    mma_f16(acc[ma][na], al, bhf[na]);
                }
            }
        }
    };

    const int S = K / 32;
    issue(0, 0);
    issue(1, 1);
    for (int s = 0; s < S; s++) {
        if (s + 1 < S) { CP_WAIT(1); } else { CP_WAIT(0); }
        __syncthreads();
        if (s + 2 < S) issue(s + 2, (s + 2) % NSTAGE);
        compute(s % NSTAGE);
    }

    // ---- epilogue ----
    const int g = lane >> 2, tig = lane & 3;
#pragma unroll
    for (int ma = 0; ma < 4; ma++) {
        const int r0 = bm + wm * 64 + ma * 16 + g;
#pragma unroll
        for (int na = 0; na < 4; na++) {
            const int c = bn + wn * 32 + na * 8 + tig * 2;
            *(float2*)(C + (size_t)r0 * DIM + c)       = make_float2(acc[ma][na][0], acc[ma][na][1]);
            *(float2*)(C + (size_t)(r0 + 8) * DIM + c) = make_float2(acc[ma][na][2], acc[ma][na][3]);
        }
    }
}

// ================= fused feature map =================
__global__ __launch_bounds__(256) void feature_both(const float* __restrict__ Q,
                                                    const float* __restrict__ Kd,
                                                    const float* __restrict__ proj,
                                                    float* __restrict__ phiq,
                                                    float* __restrict__ phik)
{
    __shared__ float XsT[64*PAD];
    __shared__ float pT[64*PAD];
    const int t = threadIdx.x;
    const int nb = ROWS / 64;
    const int is_query = (blockIdx.x < nb) ? 1 : 0;
    const int blk = is_query ? blockIdx.x : blockIdx.x - nb;
    const float* X = is_query ? Q : Kd;
    float* phi = is_query ? phiq : phik;
    const size_t base = (size_t)blk * 64 * 64;

    for (int i = t; i < 4096; i += 256) { int f_ = i >> 6, d_ = i & 63; pT[d_*PAD + f_] = proj[i]; }
    for (int i = t; i < 4096; i += 256) { int r_ = i >> 6, d_ = i & 63; XsT[d_*PAD + r_] = X[base + i]; }
    __syncthreads();

    const int r0 = (t >> 4) << 2;
    const int f0 = (t & 15) << 2;
    float acc[4][4], sq[4];
#pragma unroll
    for (int i = 0; i < 4; i++) { sq[i] = 0.f;
#pragma unroll
        for (int j = 0; j < 4; j++) acc[i][j] = 0.f; }

#pragma unroll
    for (int d = 0; d < 64; d++) {
        float4 a = *(const float4*)&XsT[d*PAD + r0];
        float4 b = *(const float4*)&pT[d*PAD + f0];
        float av[4] = {a.x, a.y, a.z, a.w};
        float bv[4] = {b.x, b.y, b.z, b.w};
#pragma unroll
        for (int i = 0; i < 4; i++) {
            sq[i] += av[i] * av[i];
#pragma unroll
            for (int j = 0; j < 4; j++) acc[i][j] += av[i] * bv[j];
        }
    }
    const float dn = 0.35355339059327373f;
    float dd[4][4];
#pragma unroll
    for (int i = 0; i < 4; i++)
#pragma unroll
        for (int j = 0; j < 4; j++) dd[i][j] = dn * acc[i][j];

    if (is_query) {
#pragma unroll
        for (int i = 0; i < 4; i++) {
            float mx = fmaxf(fmaxf(dd[i][0], dd[i][1]), fmaxf(dd[i][2], dd[i][3]));
#pragma unroll
            for (int o = 8; o >= 1; o >>= 1) mx = fmaxf(mx, __shfl_xor_sync(0xffffffffu, mx, o));
#pragma unroll
            for (int j = 0; j < 4; j++) dd[i][j] -= mx;
        }
    }
#pragma unroll
    for (int i = 0; i < 4; i++) {
        const float diag = sq[i] * (1.0f / 128.0f);
        float4 o;
        o.x = 0.125f * (expf(dd[i][0] - diag) + 1e-4f);
        o.y = 0.125f * (expf(dd[i][1] - diag) + 1e-4f);
        o.z = 0.125f * (expf(dd[i][2] - diag) + 1e-4f);
        o.w = 0.125f * (expf(dd[i][3] - diag) + 1e-4f);
        *(float4*)&phi[((size_t)blk * 64 + r0 + i) * 64 + f0] = o;
    }
}

// ================= chunk_local =================
__global__ __launch_bounds__(256) void chunk_local_kernel(const float* __restrict__ phiK,
                                                          const float* __restrict__ V,
                                                          float* __restrict__ kvloc,
                                                          float* __restrict__ kloc)
{
    __shared__ float ks[64*PAD];
    __shared__ float vs[64*PAD];
    const int t = threadIdx.x;
    const int chunk = blockIdx.x, bh = blockIdx.y;
    const size_t base = ((size_t)bh * SEQ + chunk * CH) * 64;

    for (int i = t; i < 1024; i += 256) {
        int r = i >> 4, c4 = (i & 15) << 2;
        *(float4*)&ks[r*PAD + c4] = *(const float4*)(phiK + base + (size_t)r*64 + c4);
        *(float4*)&vs[r*PAD + c4] = *(const float4*)(V    + base + (size_t)r*64 + c4);
    }
    __syncthreads();

    const int f0 = (t >> 4) << 2;
    const int c0 = (t & 15) << 2;
    float acc[4][4], kl[4];
#pragma unroll
    for (int i = 0; i < 4; i++) { kl[i] = 0.f;
#pragma unroll
        for (int j = 0; j < 4; j++) acc[i][j] = 0.f; }

#pragma unroll 8
    for (int r = 0; r < 64; r++) {
        float4 k4 = *(const float4*)&ks[r*PAD + f0];
        float4 v4 = *(const float4*)&vs[r*PAD + c0];
        float kv[4] = {k4.x, k4.y, k4.z, k4.w};
        float vv[4] = {v4.x, v4.y, v4.z, v4.w};
#pragma unroll
        for (int i = 0; i < 4; i++) {
            kl[i] += kv[i];
#pragma unroll
            for (int j = 0; j < 4; j++) acc[i][j] += kv[i] * vv[j];
        }
    }
    const size_t ob = ((size_t)bh * NCHUNK + chunk) * (64*64);
#pragma unroll
    for (int i = 0; i < 4; i++)
        *(float4*)&kvloc[ob + (size_t)(f0+i)*64 + c0] =
            make_float4(acc[i][0], acc[i][1], acc[i][2], acc[i][3]);
    if ((t & 15) == 0) {
        const size_t kb = ((size_t)bh * NCHUNK + chunk) * 64 + f0;
#pragma unroll
        for (int i = 0; i < 4; i++) kloc[kb + i] = kl[i];
    }
}

// ================= prefix =================
__global__ __launch_bounds__(256) void prefix_kernel(float* __restrict__ kvloc,
                                                     float* __restrict__ kloc)
{
    const int g = blockIdx.x, bh = blockIdx.y;
    const int t = threadIdx.x;
    const int e = g * 256 + t;
    float run = 0.f;
    for (int c = 0; c < NCHUNK; c++) {
        const size_t idx = ((size_t)bh * NCHUNK + c) * 4096 + e;
        float v = kvloc[idx];
        kvloc[idx] = run;
        run += v;
    }
    if (g == 0 && t < 64) {
        float rk = 0.f;
        for (int c = 0; c < NCHUNK; c++) {
            const size_t b = ((size_t)bh * NCHUNK + c) * 64 + t;
            float v = kloc[b];
            kloc[b] = rk;
            rk += v;
        }
    }
}

// ================= chunk_out =================
__global__ __launch_bounds__(256) void chunk_out_kernel(const float* __restrict__ phiQ,
                                                        const float* __restrict__ phiK,
                                                        const float* __restrict__ Vg,
                                                        const float* __restrict__ KVp,
                                                        const float* __restrict__ Kp,
                                                        const float* __restrict__ Wpost,
                                                        __half* __restrict__ ahi,
                                                        __half* __restrict__ alo)
{
    extern __shared__ float sm[];
    float* QsT = sm;
    float* KsT = QsT + 64*PAD;
    float* Vs  = KsT + 64*PAD;
    float* KVs = Vs  + 64*PAD;
    float* Ss  = KVs + 64*PAD;
    float* Wps = Ss  + 64*PAD;
    float* den = Wps + 64*PAD;
    float* kps = den + 64;

    const int t = threadIdx.x;
    const int chunk = blockIdx.x, bh = blockIdx.y;
    const size_t base   = ((size_t)bh * SEQ + chunk * CH) * 64;
    const size_t kvbase = ((size_t)bh * NCHUNK + chunk) * 4096;

    for (int i = t; i < 1024; i += 256) {
        int r = i >> 4, c4 = (i & 15) << 2;
        float4 q = *(const float4*)(phiQ + base + (size_t)r*64 + c4);
        float4 k = *(const float4*)(phiK + base + (size_t)r*64 + c4);
        float4 w = *(const float4*)(Wpost + (size_t)r*64 + c4);
        QsT[(c4+0)*PAD + r] = q.x; QsT[(c4+1)*PAD + r] = q.y;
        QsT[(c4+2)*PAD + r] = q.z; QsT[(c4+3)*PAD + r] = q.w;
        KsT[(c4+0)*PAD + r] = k.x; KsT[(c4+1)*PAD + r] = k.y;
        KsT[(c4+2)*PAD + r] = k.z; KsT[(c4+3)*PAD + r] = k.w;
        Wps[(c4+0)*PAD + r] = w.x; Wps[(c4+1)*PAD + r] = w.y;
        Wps[(c4+2)*PAD + r] = w.z; Wps[(c4+3)*PAD + r] = w.w;
        *(float4*)&Vs [r*PAD + c4] = *(const float4*)(Vg  + base   + (size_t)r*64 + c4);
        *(float4*)&KVs[r*PAD + c4] = *(const float4*)(KVp + kvbase + (size_t)r*64 + c4);
    }
    if (t < 64) kps[t] = Kp[((size_t)bh * NCHUNK + chunk) * 64 + t];
    __syncthreads();

    const int r0 = (t >> 4) << 2;
    const int c0 = (t & 15) << 2;

    // ---- Phase S ----
    float sacc[4][4], kq[4];
#pragma unroll
    for (int i = 0; i < 4; i++) { kq[i] = 0.f;
#pragma unroll
        for (int j = 0; j < 4; j++) sacc[i][j] = 0.f; }
#pragma unroll 8
    for (int d = 0; d < 64; d++) {
        float4 q4 = *(const float4*)&QsT[d*PAD + r0];
        float4 k4 = *(const float4*)&KsT[d*PAD + c0];
        float kp = kps[d];
        float qv[4] = {q4.x, q4.y, q4.z, q4.w};
        float kv[4] = {k4.x, k4.y, k4.z, k4.w};
#pragma unroll
        for (int i = 0; i < 4; i++) {
            kq[i] += qv[i] * kp;
#pragma unroll
            for (int j = 0; j < 4; j++) sacc[i][j] += qv[i] * kv[j];
        }
    }
    float rs[4];
#pragma unroll
    for (int i = 0; i < 4; i++) {
        const int r = r0 + i;
        float m0 = (c0+0 <= r) ? sacc[i][0] : 0.f;
        float m1 = (c0+1 <= r) ? sacc[i][1] : 0.f;
        float m2 = (c0+2 <= r) ? sacc[i][2] : 0.f;
        float m3 = (c0+3 <= r) ? sacc[i][3] : 0.f;
        *(float4*)&Ss[r*PAD + c0] = make_float4(m0, m1, m2, m3);
        rs[i] = m0 + m1 + m2 + m3;
    }
#pragma unroll
    for (int o = 8; o >= 1; o >>= 1)
#pragma unroll
        for (int i = 0; i < 4; i++) rs[i] += __shfl_xor_sync(0xffffffffu, rs[i], o);
    if ((t & 15) == 0) {
#pragma unroll
        for (int i = 0; i < 4; i++) den[r0 + i] = fmaxf(rs[i] + kq[i], 1e-6f);
    }
    __syncthreads();

    // ---- Phase O ----
    float oacc[4][4];
#pragma unroll
    for (int i = 0; i < 4; i++)
#pragma unroll
        for (int j = 0; j < 4; j++) oacc[i][j] = 0.f;
#pragma unroll 4
    for (int j0 = 0; j0 < 64; j0 += 4) {
        float4 s4[4], v4[4];
#pragma unroll
        for (int i = 0; i < 4; i++)  s4[i]  = *(const float4*)&Ss[(r0+i)*PAD + j0];
#pragma unroll
        for (int jj = 0; jj < 4; jj++) v4[jj] = *(const float4*)&Vs[(j0+jj)*PAD + c0];
#pragma unroll
        for (int i = 0; i < 4; i++) {
            float sv[4] = {s4[i].x, s4[i].y, s4[i].z, s4[i].w};
#pragma unroll
            for (int jj = 0; jj < 4; jj++) {
                oacc[i][0] += sv[jj] * (&v4[jj].x)[0];
                oacc[i][1] += sv[jj] * (&v4[jj].x)[1];
                oacc[i][2] += sv[jj] * (&v4[jj].x)[2];
                oacc[i][3] += sv[jj] * (&v4[jj].x)[3];
            }
        }
    }
#pragma unroll 4
    for (int f0 = 0; f0 < 64; f0 += 4) {
        float4 q4[4], kv4[4];
#pragma unroll
        for (int jj = 0; jj < 4; jj++) {
            q4[jj]  = *(const float4*)&QsT[(f0+jj)*PAD + r0];
            kv4[jj] = *(const float4*)&KVs[(f0+jj)*PAD + c0];
        }
#pragma unroll
        for (int jj = 0; jj < 4; jj++) {
            float qv[4] = {q4[jj].x, q4[jj].y, q4[jj].z, q4[jj].w};
#pragma unroll
            for (int i = 0; i < 4; i++) {
                oacc[i][0] += qv[i] * (&kv4[jj].x)[0];
                oacc[i][1] += qv[i] * (&kv4[jj].x)[1];
                oacc[i][2] += qv[i] * (&kv4[jj].x)[2];
                oacc[i][3] += qv[i] * (&kv4[jj].x)[3];
            }
        }
    }
#pragma unroll
    for (int i = 0; i < 4; i++) {
        const float inv = 1.0f / den[r0 + i];
#pragma unroll
        for (int j = 0; j < 4; j++) oacc[i][j] *= inv;
    }
    __syncthreads();
#pragma unroll
    for (int i = 0; i < 4; i++)
        *(float4*)&Ss[(r0+i)*PAD + c0] = make_float4(oacc[i][0], oacc[i][1], oacc[i][2], oacc[i][3]);
    __syncthreads();

    // ---- Phase W ----
    float facc[4][4];
#pragma unroll
    for (int i = 0; i < 4; i++)
#pragma unroll
        for (int j = 0; j < 4; j++) facc[i][j] = 0.f;
#pragma unroll 4
    for (int cg = 0; cg < 64; cg += 4) {
        float4 o4[4], w4[4];
#pragma unroll
        for (int i = 0; i < 4; i++)   o4[i]  = *(const float4*)&Ss[(r0+i)*PAD + cg];
#pragma unroll
        for (int jj = 0; jj < 4; jj++) w4[jj] = *(const float4*)&Wps[(cg+jj)*PAD + c0];
#pragma unroll
        for (int i = 0; i < 4; i++) {
            float ov[4] = {o4[i].x, o4[i].y, o4[i].z, o4[i].w};
#pragma unroll
            for (int jj = 0; jj < 4; jj++) {
                facc[i][0] += ov[jj] * (&w4[jj].x)[0];
                facc[i][1] += ov[jj] * (&w4[jj].x)[1];
                facc[i][2] += ov[jj] * (&w4[jj].x)[2];
                facc[i][3] += ov[jj] * (&w4[jj].x)[3];
            }
        }
    }

    // ---- store with head-transpose + fp16 split ----
    const int bi = bh >> 4, hi2 = bh & 15;
#pragma unroll
    for (int i = 0; i < 4; i++) {
        const int si = chunk * CH + r0 + i;
        const size_t ob = ((size_t)bi * SEQ + si) * DIM + hi2 * 64 + c0;
        __half2 hp[2], lp[2];
#pragma unroll
        for (int j = 0; j < 2; j++) {
            float fa = facc[i][2*j], fb = facc[i][2*j+1];
            __half ha = __float2half(fa);
            __half hb = __float2half(fb);
            hp[j].x = ha; hp[j].y = hb;
            lp[j].x = __float2half(fa - __half2float(ha));
            lp[j].y = __float2half(fb - __half2float(hb));
        }
        *(float2*)(ahi + ob) = *(float2*)hp;
        *(float2*)(alo + ob) = *(float2*)lp;
    }
}

// ================= launch =================
extern "C" void kernel_launch(void* const* d_in, const int* in_sizes, int n_in,
                              void* d_out, int out_size)
{
    const float* x     = (const float*)d_in[0];
    const float* Wq    = (const float*)d_in[1];
    const float* Wk    = (const float*)d_in[2];
    const float* Wv    = (const float*)d_in[3];
    const float* proj  = (const float*)d_in[4];
    const float* Wpost = (const float*)d_in[5];
    const float* Wout  = (const float*)d_in[6];
    float* out = (float*)d_out;

    float *pQ, *pK, *pV, *pphiq, *pphik, *pkv, *pks;
    __half *pxhi, *pxlo, *pahi, *palo, *pwh;
    cudaGetSymbolAddress((void**)&pQ, g_Q);
    cudaGetSymbolAddress((void**)&pK, g_K);
    cudaGetSymbolAddress((void**)&pV, g_V);
    cudaGetSymbolAddress((void**)&pphiq, g_phiq);
    cudaGetSymbolAddress((void**)&pphik, g_phik);
    cudaGetSymbolAddress((void**)&pkv, g_kv);
    cudaGetSymbolAddress((void**)&pks, g_ks);
    cudaGetSymbolAddress((void**)&pxhi, g_xhi);
    cudaGetSymbolAddress((void**)&pxlo, g_xlo);
    cudaGetSymbolAddress((void**)&pahi, g_ahi);
    cudaGetSymbolAddress((void**)&palo, g_alo);
    cudaGetSymbolAddress((void**)&pwh, g_wh);

    static const size_t chunk_smem = (size_t)(6*64*PAD + 128) * sizeof(float);
    cudaFuncSetAttribute(chunk_out_kernel, cudaFuncAttributeMaxDynamicSharedMemorySize,
                         (int)chunk_smem);
    static const int gemm_smem = NSTAGE * BUFB;     // 92160 B
    cudaFuncSetAttribute(gemm_hmma_split, cudaFuncAttributeMaxDynamicSharedMemorySize, gemm_smem);

    convert_all<<<12288, 256>>>(x, Wq, Wk, Wv, Wout, pxhi, pxlo, pwh);

    dim3 gqkv(24, MROWS/128);
    gemm_hmma_split<<<gqkv, 256, gemm_smem>>>(pxhi, pxlo, pwh, pQ, pK, pV, DIM);

    feature_both<<<2*(ROWS/64), 256>>>(pQ, pK, proj, pphiq, pphik);

    dim3 gc(NCHUNK, NBH);
    chunk_local_kernel<<<gc, 256>>>(pphik, pV, pkv, pks);
    dim3 gp(16, NBH);
    prefix_kernel<<<gp, 256>>>(pkv, pks);
    chunk_out_kernel<<<gc, 256, chunk_smem>>>(pphiq, pphik, pV, pkv, pks, Wpost, pahi, palo);

    dim3 gout(8, MROWS/128);
    gemm_hmma_split<<<gout, 256, gemm_smem>>>(pahi, palo, pwh + 3*DIM*DIM, out, out, out, DIM);
}

// round 13
// speedup vs baseline: 1.3155x; 1.0182x over previous
#include <cuda_runtime.h>
#include <cuda_fp16.h>
#include <math.h>
#include <cstdint>

// Problem constants
#define BATCH 4
#define SEQ   2048
#define DIM   1024
#define HEADS 16
#define DH    64
#define NF    64
#define NBH   (BATCH*HEADS)          // 64
#define ROWS  (NBH*SEQ)              // 131072 head-rows
#define MROWS (BATCH*SEQ)            // 8192 GEMM rows
#define CH    64                     // chunk length
#define NCHUNK (SEQ/CH)              // 32
#define PAD   68

// ---------------- device scratch ----------------
__device__ float g_Q[ROWS*DH];
__device__ float g_K[ROWS*DH];
__device__ float g_V[ROWS*DH];
__device__ float g_phiq[ROWS*NF];
__device__ float g_phik[ROWS*NF];
__device__ float g_kv[NBH*NCHUNK*NF*DH];
__device__ float g_ks[NBH*NCHUNK*NF];
// fp16 split buffers (A-side split, B single)
__device__ __half g_xhi[MROWS*DIM];
__device__ __half g_xlo[MROWS*DIM];
__device__ __half g_ahi[MROWS*DIM];
__device__ __half g_alo[MROWS*DIM];
__device__ __half g_wh[4*DIM*DIM];   // slots 0-2: Wq/Wk/Wv ; slot 3: W2 = fold(Wout, Wpost)

// ================= helpers =================
__device__ __forceinline__ uint32_t smem_u32(const void* p) {
    uint32_t a;
    asm("{ .reg .u64 tmp; cvta.to.shared.u64 tmp, %1; cvt.u32.u64 %0, tmp; }" : "=r"(a) : "l"(p));
    return a;
}
__device__ __forceinline__ void ldm_x4(uint32_t* r, uint32_t addr) {
    asm volatile("ldmatrix.sync.aligned.m8n8.x4.shared.b16 {%0,%1,%2,%3}, [%4];"
        : "=r"(r[0]), "=r"(r[1]), "=r"(r[2]), "=r"(r[3]) : "r"(addr));
}
__device__ __forceinline__ void mma_f16(float* d, const uint32_t* a, const uint32_t* b) {
    asm volatile("mma.sync.aligned.m16n8k16.row.col.f32.f16.f16.f32 "
        "{%0,%1,%2,%3}, {%4,%5,%6,%7}, {%8,%9}, {%0,%1,%2,%3};"
        : "+f"(d[0]), "+f"(d[1]), "+f"(d[2]), "+f"(d[3])
        : "r"(a[0]), "r"(a[1]), "r"(a[2]), "r"(a[3]), "r"(b[0]), "r"(b[1]));
}
__device__ __forceinline__ void cp16(uint32_t dst, const void* src) {
    asm volatile("cp.async.cg.shared.global [%0], [%1], 16;" :: "r"(dst), "l"(src));
}
#define CP_COMMIT() asm volatile("cp.async.commit_group;" ::: "memory")
#define CP_WAIT(N)  asm volatile("cp.async.wait_group %0;" :: "n"(N) : "memory")

// ================= fused conversion: x -> fp16 split, Wq/Wk/Wv -> fp16 =================
__global__ __launch_bounds__(256) void convert_all(
    const float* __restrict__ x,
    const float* __restrict__ Wq, const float* __restrict__ Wk,
    const float* __restrict__ Wv,
    __half* __restrict__ xhi, __half* __restrict__ xlo,
    __half* __restrict__ wh)
{
    const int b = blockIdx.x;
    if (b < 8192) {
        const int i = b * 256 + threadIdx.x;
        float4 v = ((const float4*)x)[i];
        __half h0 = __float2half(v.x), h1 = __float2half(v.y);
        __half h2 = __float2half(v.z), h3 = __float2half(v.w);
        __half2 p;
        p.x = h0; p.y = h1; ((__half2*)xhi)[2*i]   = p;
        p.x = h2; p.y = h3; ((__half2*)xhi)[2*i+1] = p;
        p.x = __float2half(v.x - __half2float(h0));
        p.y = __float2half(v.y - __half2float(h1));
        ((__half2*)xlo)[2*i] = p;
        p.x = __float2half(v.z - __half2float(h2));
        p.y = __float2half(v.w - __half2float(h3));
        ((__half2*)xlo)[2*i+1] = p;
    } else {
        const int wb = b - 8192;
        const int w = wb >> 10;          // 0..2
        const int r = wb & 1023;
        const float* src = (w == 0) ? Wq : (w == 1) ? Wk : Wv;
        __half* hi = wh + (size_t)w * DIM * DIM;
        const int i = r * 256 + threadIdx.x;
        float4 v = ((const float4*)src)[i];
        __half2 p;
        p.x = __float2half(v.x); p.y = __float2half(v.y);
        ((__half2*)hi)[2*i] = p;
        p.x = __float2half(v.z); p.y = __float2half(v.w);
        ((__half2*)hi)[2*i+1] = p;
    }
}

// ================= W2 = per-head fold of Wout @ Wpost =================
// W2[o, h*64+c] = sum_e Wout[o, h*64+e] * Wpost[e, c]  -> fp16 into wh slot 3
// 64-row o-tile: smem = 64*64*4 + 64*68*4 = 33792 B (< 48KB static limit)
__global__ __launch_bounds__(256) void w2_kernel(const float* __restrict__ Wout,
                                                 const float* __restrict__ Wpost,
                                                 __half* __restrict__ w2h)
{
    __shared__ float Wo[64*64];      // Wout[o0+r][h*64+e]
    __shared__ float Wp[64*68];      // Wpost[e][c] padded
    const int h = blockIdx.y;
    const int o0 = blockIdx.x * 64;
    const int t = threadIdx.x;

    for (int i = t; i < 4096; i += 256) {
        int r = i >> 6, e = i & 63;
        Wo[i] = Wout[(size_t)(o0 + r) * DIM + h * 64 + e];
        int e2 = i >> 6, c = i & 63;
        Wp[e2*68 + c] = Wpost[i];
    }
    __syncthreads();

    const int r0 = (t >> 4) * 4;     // 4 rows
    const int c0 = (t & 15) * 4;     // 4 cols
    float acc[4][4];
#pragma unroll
    for (int i = 0; i < 4; i++)
#pragma unroll
        for (int j = 0; j < 4; j++) acc[i][j] = 0.f;
#pragma unroll 8
    for (int e = 0; e < 64; e++) {
        float4 wp = *(const float4*)&Wp[e*68 + c0];
#pragma unroll
        for (int i = 0; i < 4; i++) {
            float a = Wo[(r0 + i)*64 + e];
            acc[i][0] += a * wp.x; acc[i][1] += a * wp.y;
            acc[i][2] += a * wp.z; acc[i][3] += a * wp.w;
        }
    }
#pragma unroll
    for (int i = 0; i < 4; i++) {
        __half2 p0, p1;
        p0.x = __float2half(acc[i][0]); p0.y = __float2half(acc[i][1]);
        p1.x = __float2half(acc[i][2]); p1.y = __float2half(acc[i][3]);
        __half* dst = w2h + (size_t)(o0 + r0 + i) * DIM + h * 64 + c0;
        *(__half2*)dst = p0;
        *(__half2*)(dst + 2) = p1;
    }
}

// ================= HMMA fp16 A-split GEMM: 128x128 tile, 3-stage, 2 CTA/SM =================
#define TS 10240                       // one 128x32 fp16 tile @ 80B row stride
#define BUFB (3*TS)                    // Ah, Al, Bh per stage (30720 B)
#define NSTAGE 3

__global__ __launch_bounds__(256, 2) void gemm_hmma_split(
    const __half* __restrict__ Ahi, const __half* __restrict__ Alo,
    const __half* __restrict__ Bh_all,
    float* __restrict__ C0, float* __restrict__ C1, float* __restrict__ C2, int K)
{
    extern __shared__ char smx[];
    const int t = threadIdx.x;
    const int wid = t >> 5, lane = t & 31;
    const int wm = wid >> 2, wn = wid & 3;          // 2m x 4n, warp tile 64x32
    const int bm = blockIdx.y * 128;
    const int which = blockIdx.x >> 3;
    const int bn = (blockIdx.x & 7) * 128;
    const __half* Bh = Bh_all + (size_t)which * DIM * DIM;
    float* C = (which == 0) ? C0 : (which == 1) ? C1 : C2;

    const uint32_t smb = smem_u32(smx);
    const __half* srcs[3] = {Ahi, Alo, Bh};

    float acc[4][4][4];
#pragma unroll
    for (int i = 0; i < 4; i++)
#pragma unroll
        for (int j = 0; j < 4; j++)
#pragma unroll
            for (int q = 0; q < 4; q++) acc[i][j][q] = 0.f;

    auto issue = [&](int s, int b) {
        const int k0 = s * 32;
#pragma unroll
        for (int q = 0; q < 6; q++) {
            const int tile = q >> 1;
            const int i = (q & 1) * 256 + t;
            const int r = i >> 2, ch = i & 3;
            const int rb = (tile < 2) ? bm : bn;
            cp16(smb + b * BUFB + tile * TS + r * 80 + ch * 16,
                 srcs[tile] + (size_t)(rb + r) * K + k0 + ch * 8);
        }
        CP_COMMIT();
    };

    auto compute = [&](int b) {
        const uint32_t Ahb = smb + b * BUFB;
        const uint32_t Alb = Ahb + TS;
        const uint32_t Bhb = Ahb + 2 * TS;
        const int lrA = lane & 15, kbA = lane >> 4;
        const int nrB = (lane & 7) + ((lane >> 4) << 3);
        const int kbB = (lane >> 3) & 1;
#pragma unroll
        for (int ks = 0; ks < 2; ks++) {
            uint32_t bhf[4][2];
#pragma unroll
            for (int np = 0; np < 2; np++) {
                uint32_t off = (uint32_t)((wn * 32 + np * 16 + nrB) * 80 + ks * 32 + kbB * 16);
                uint32_t tmp[4];
                ldm_x4(tmp, Bhb + off);
                bhf[2*np][0] = tmp[0]; bhf[2*np][1] = tmp[1];
                bhf[2*np+1][0] = tmp[2]; bhf[2*np+1][1] = tmp[3];
            }
#pragma unroll
            for (int ma = 0; ma < 4; ma++) {
                uint32_t ah[4], al[4];
                uint32_t off = (uint32_t)((wm * 64 + ma * 16 + lrA) * 80 + ks * 32 + kbA * 16);
                ldm_x4(ah, Ahb + off);
                ldm_x4(al, Alb + off);
#pragma unroll
                for (int na = 0; na < 4; na++) {
                    mma_f16(acc[ma][na], ah, bhf[na]);
                    mma_f16(acc[ma][na], al, bhf[na]);
                }
            }
        }
    };

    const int S = K / 32;
    issue(0, 0);
    issue(1, 1);
    for (int s = 0; s < S; s++) {
        if (s + 1 < S) { CP_WAIT(1); } else { CP_WAIT(0); }
        __syncthreads();
        if (s + 2 < S) issue(s + 2, (s + 2) % NSTAGE);
        compute(s % NSTAGE);
    }

    const int g = lane >> 2, tig = lane & 3;
#pragma unroll
    for (int ma = 0; ma < 4; ma++) {
        const int r0 = bm + wm * 64 + ma * 16 + g;
#pragma unroll
        for (int na = 0; na < 4; na++) {
            const int c = bn + wn * 32 + na * 8 + tig * 2;
            *(float2*)(C + (size_t)r0 * DIM + c)       = make_float2(acc[ma][na][0], acc[ma][na][1]);
            *(float2*)(C + (size_t)(r0 + 8) * DIM + c) = make_float2(acc[ma][na][2], acc[ma][na][3]);
        }
    }
}

// ================= fused feature map (fast exp) =================
__global__ __launch_bounds__(256) void feature_both(const float* __restrict__ Q,
                                                    const float* __restrict__ Kd,
                                                    const float* __restrict__ proj,
                                                    float* __restrict__ phiq,
                                                    float* __restrict__ phik)
{
    __shared__ float XsT[64*PAD];
    __shared__ float pT[64*PAD];
    const int t = threadIdx.x;
    const int nb = ROWS / 64;
    const int is_query = (blockIdx.x < nb) ? 1 : 0;
    const int blk = is_query ? blockIdx.x : blockIdx.x - nb;
    const float* X = is_query ? Q : Kd;
    float* phi = is_query ? phiq : phik;
    const size_t base = (size_t)blk * 64 * 64;

    for (int i = t; i < 4096; i += 256) { int f_ = i >> 6, d_ = i & 63; pT[d_*PAD + f_] = proj[i]; }
    for (int i = t; i < 4096; i += 256) { int r_ = i >> 6, d_ = i & 63; XsT[d_*PAD + r_] = X[base + i]; }
    __syncthreads();

    const int r0 = (t >> 4) << 2;
    const int f0 = (t & 15) << 2;
    float acc[4][4], sq[4];
#pragma unroll
    for (int i = 0; i < 4; i++) { sq[i] = 0.f;
#pragma unroll
        for (int j = 0; j < 4; j++) acc[i][j] = 0.f; }

#pragma unroll
    for (int d = 0; d < 64; d++) {
        float4 a = *(const float4*)&XsT[d*PAD + r0];
        float4 b = *(const float4*)&pT[d*PAD + f0];
        float av[4] = {a.x, a.y, a.z, a.w};
        float bv[4] = {b.x, b.y, b.z, b.w};
#pragma unroll
        for (int i = 0; i < 4; i++) {
            sq[i] += av[i] * av[i];
#pragma unroll
            for (int j = 0; j < 4; j++) acc[i][j] += av[i] * bv[j];
        }
    }
    const float dn = 0.35355339059327373f;
    float dd[4][4];
#pragma unroll
    for (int i = 0; i < 4; i++)
#pragma unroll
        for (int j = 0; j < 4; j++) dd[i][j] = dn * acc[i][j];

    if (is_query) {
#pragma unroll
        for (int i = 0; i < 4; i++) {
            float mx = fmaxf(fmaxf(dd[i][0], dd[i][1]), fmaxf(dd[i][2], dd[i][3]));
#pragma unroll
            for (int o = 8; o >= 1; o >>= 1) mx = fmaxf(mx, __shfl_xor_sync(0xffffffffu, mx, o));
#pragma unroll
            for (int j = 0; j < 4; j++) dd[i][j] -= mx;
        }
    }
#pragma unroll
    for (int i = 0; i < 4; i++) {
        const float diag = sq[i] * (1.0f / 128.0f);
        float4 o;
        o.x = 0.125f * (__expf(dd[i][0] - diag) + 1e-4f);
        o.y = 0.125f * (__expf(dd[i][1] - diag) + 1e-4f);
        o.z = 0.125f * (__expf(dd[i][2] - diag) + 1e-4f);
        o.w = 0.125f * (__expf(dd[i][3] - diag) + 1e-4f);
        *(float4*)&phi[((size_t)blk * 64 + r0 + i) * 64 + f0] = o;
    }
}

// ================= chunk_local =================
__global__ __launch_bounds__(256) void chunk_local_kernel(const float* __restrict__ phiK,
                                                          const float* __restrict__ V,
                                                          float* __restrict__ kvloc,
                                                          float* __restrict__ kloc)
{
    __shared__ float ks[64*PAD];
    __shared__ float vs[64*PAD];
    const int t = threadIdx.x;
    const int chunk = blockIdx.x, bh = blockIdx.y;
    const size_t base = ((size_t)bh * SEQ + chunk * CH) * 64;

    for (int i = t; i < 1024; i += 256) {
        int r = i >> 4, c4 = (i & 15) << 2;
        *(float4*)&ks[r*PAD + c4] = *(const float4*)(phiK + base + (size_t)r*64 + c4);
        *(float4*)&vs[r*PAD + c4] = *(const float4*)(V    + base + (size_t)r*64 + c4);
    }
    __syncthreads();

    const int f0 = (t >> 4) << 2;
    const int c0 = (t & 15) << 2;
    float acc[4][4], kl[4];
#pragma unroll
    for (int i = 0; i < 4; i++) { kl[i] = 0.f;
#pragma unroll
        for (int j = 0; j < 4; j++) acc[i][j] = 0.f; }

#pragma unroll 8
    for (int r = 0; r < 64; r++) {
        float4 k4 = *(const float4*)&ks[r*PAD + f0];
        float4 v4 = *(const float4*)&vs[r*PAD + c0];
        float kv[4] = {k4.x, k4.y, k4.z, k4.w};
        float vv[4] = {v4.x, v4.y, v4.z, v4.w};
#pragma unroll
        for (int i = 0; i < 4; i++) {
            kl[i] += kv[i];
#pragma unroll
            for (int j = 0; j < 4; j++) acc[i][j] += kv[i] * vv[j];
        }
    }
    const size_t ob = ((size_t)bh * NCHUNK + chunk) * (64*64);
#pragma unroll
    for (int i = 0; i < 4; i++)
        *(float4*)&kvloc[ob + (size_t)(f0+i)*64 + c0] =
            make_float4(acc[i][0], acc[i][1], acc[i][2], acc[i][3]);
    if ((t & 15) == 0) {
        const size_t kb = ((size_t)bh * NCHUNK + chunk) * 64 + f0;
#pragma unroll
        for (int i = 0; i < 4; i++) kloc[kb + i] = kl[i];
    }
}

// ================= prefix =================
__global__ __launch_bounds__(256) void prefix_kernel(float* __restrict__ kvloc,
                                                     float* __restrict__ kloc)
{
    const int g = blockIdx.x, bh = blockIdx.y;
    const int t = threadIdx.x;
    const int e = g * 256 + t;
    float run = 0.f;
    for (int c = 0; c < NCHUNK; c++) {
        const size_t idx = ((size_t)bh * NCHUNK + c) * 4096 + e;
        float v = kvloc[idx];
        kvloc[idx] = run;
        run += v;
    }
    if (g == 0 && t < 64) {
        float rk = 0.f;
        for (int c = 0; c < NCHUNK; c++) {
            const size_t b = ((size_t)bh * NCHUNK + c) * 64 + t;
            float v = kloc[b];
            kloc[b] = rk;
            rk += v;
        }
    }
}

// ================= chunk_out (no Wpost phase — folded into W2) =================
__global__ __launch_bounds__(256) void chunk_out_kernel(const float* __restrict__ phiQ,
                                                        const float* __restrict__ phiK,
                                                        const float* __restrict__ Vg,
                                                        const float* __restrict__ KVp,
                                                        const float* __restrict__ Kp,
                                                        __half* __restrict__ ahi,
                                                        __half* __restrict__ alo)
{
    extern __shared__ float sm[];
    float* QsT = sm;
    float* KsT = QsT + 64*PAD;
    float* Vs  = KsT + 64*PAD;
    float* KVs = Vs  + 64*PAD;
    float* Ss  = KVs + 64*PAD;
    float* den = Ss  + 64*PAD;
    float* kps = den + 64;

    const int t = threadIdx.x;
    const int chunk = blockIdx.x, bh = blockIdx.y;
    const size_t base   = ((size_t)bh * SEQ + chunk * CH) * 64;
    const size_t kvbase = ((size_t)bh * NCHUNK + chunk) * 4096;

    for (int i = t; i < 1024; i += 256) {
        int r = i >> 4, c4 = (i & 15) << 2;
        float4 q = *(const float4*)(phiQ + base + (size_t)r*64 + c4);
        float4 k = *(const float4*)(phiK + base + (size_t)r*64 + c4);
        QsT[(c4+0)*PAD + r] = q.x; QsT[(c4+1)*PAD + r] = q.y;
        QsT[(c4+2)*PAD + r] = q.z; QsT[(c4+3)*PAD + r] = q.w;
        KsT[(c4+0)*PAD + r] = k.x; KsT[(c4+1)*PAD + r] = k.y;
        KsT[(c4+2)*PAD + r] = k.z; KsT[(c4+3)*PAD + r] = k.w;
        *(float4*)&Vs [r*PAD + c4] = *(const float4*)(Vg  + base   + (size_t)r*64 + c4);
        *(float4*)&KVs[r*PAD + c4] = *(const float4*)(KVp + kvbase + (size_t)r*64 + c4);
    }
    if (t < 64) kps[t] = Kp[((size_t)bh * NCHUNK + chunk) * 64 + t];
    __syncthreads();

    const int r0 = (t >> 4) << 2;
    const int c0 = (t & 15) << 2;

    // ---- Phase S ----
    float sacc[4][4], kq[4];
#pragma unroll
    for (int i = 0; i < 4; i++) { kq[i] = 0.f;
#pragma unroll
        for (int j = 0; j < 4; j++) sacc[i][j] = 0.f; }
#pragma unroll 8
    for (int d = 0; d < 64; d++) {
        float4 q4 = *(const float4*)&QsT[d*PAD + r0];
        float4 k4 = *(const float4*)&KsT[d*PAD + c0];
        float kp = kps[d];
        float qv[4] = {q4.x, q4.y, q4.z, q4.w};
        float kv[4] = {k4.x, k4.y, k4.z, k4.w};
#pragma unroll
        for (int i = 0; i < 4; i++) {
            kq[i] += qv[i] * kp;
#pragma unroll
            for (int j = 0; j < 4; j++) sacc[i][j] += qv[i] * kv[j];
        }
    }
    float rs[4];
#pragma unroll
    for (int i = 0; i < 4; i++) {
        const int r = r0 + i;
        float m0 = (c0+0 <= r) ? sacc[i][0] : 0.f;
        float m1 = (c0+1 <= r) ? sacc[i][1] : 0.f;
        float m2 = (c0+2 <= r) ? sacc[i][2] : 0.f;
        float m3 = (c0+3 <= r) ? sacc[i][3] : 0.f;
        *(float4*)&Ss[r*PAD + c0] = make_float4(m0, m1, m2, m3);
        rs[i] = m0 + m1 + m2 + m3;
    }
#pragma unroll
    for (int o = 8; o >= 1; o >>= 1)
#pragma unroll
        for (int i = 0; i < 4; i++) rs[i] += __shfl_xor_sync(0xffffffffu, rs[i], o);
    if ((t & 15) == 0) {
#pragma unroll
        for (int i = 0; i < 4; i++) den[r0 + i] = fmaxf(rs[i] + kq[i], 1e-6f);
    }
    __syncthreads();

    // ---- Phase O: G = (S V + Q KVprev) / den ----
    float oacc[4][4];
#pragma unroll
    for (int i = 0; i < 4; i++)
#pragma unroll
        for (int j = 0; j < 4; j++) oacc[i][j] = 0.f;
#pragma unroll 4
    for (int j0 = 0; j0 < 64; j0 += 4) {
        float4 s4[4], v4[4];
#pragma unroll
        for (int i = 0; i < 4; i++)  s4[i]  = *(const float4*)&Ss[(r0+i)*PAD + j0];
#pragma unroll
        for (int jj = 0; jj < 4; jj++) v4[jj] = *(const float4*)&Vs[(j0+jj)*PAD + c0];
#pragma unroll
        for (int i = 0; i < 4; i++) {
            float sv[4] = {s4[i].x, s4[i].y, s4[i].z, s4[i].w};
#pragma unroll
            for (int jj = 0; jj < 4; jj++) {
                oacc[i][0] += sv[jj] * (&v4[jj].x)[0];
                oacc[i][1] += sv[jj] * (&v4[jj].x)[1];
                oacc[i][2] += sv[jj] * (&v4[jj].x)[2];
                oacc[i][3] += sv[jj] * (&v4[jj].x)[3];
            }
        }
    }
#pragma unroll 4
    for (int f0 = 0; f0 < 64; f0 += 4) {
        float4 q4[4], kv4[4];
#pragma unroll
        for (int jj = 0; jj < 4; jj++) {
            q4[jj]  = *(const float4*)&QsT[(f0+jj)*PAD + r0];
            kv4[jj] = *(const float4*)&KVs[(f0+jj)*PAD + c0];
        }
#pragma unroll
        for (int jj = 0; jj < 4; jj++) {
            float qv[4] = {q4[jj].x, q4[jj].y, q4[jj].z, q4[jj].w};
#pragma unroll
            for (int i = 0; i < 4; i++) {
                oacc[i][0] += qv[i] * (&kv4[jj].x)[0];
                oacc[i][1] += qv[i] * (&kv4[jj].x)[1];
                oacc[i][2] += qv[i] * (&kv4[jj].x)[2];
                oacc[i][3] += qv[i] * (&kv4[jj].x)[3];
            }
        }
    }

    // ---- store G with head-transpose + fp16 split ----
    const int bi = bh >> 4, hi2 = bh & 15;
#pragma unroll
    for (int i = 0; i < 4; i++) {
        const float inv = 1.0f / den[r0 + i];
        const int si = chunk * CH + r0 + i;
        const size_t ob = ((size_t)bi * SEQ + si) * DIM + hi2 * 64 + c0;
        __half2 hp[2], lp[2];
#pragma unroll
        for (int j = 0; j < 2; j++) {
            float fa = oacc[i][2*j] * inv, fb = oacc[i][2*j+1] * inv;
            __half ha = __float2half(fa);
            __half hb = __float2half(fb);
            hp[j].x = ha; hp[j].y = hb;
            lp[j].x = __float2half(fa - __half2float(ha));
            lp[j].y = __float2half(fb - __half2float(hb));
        }
        *(float2*)(ahi + ob) = *(float2*)hp;
        *(float2*)(alo + ob) = *(float2*)lp;
    }
}

// ================= launch =================
extern "C" void kernel_launch(void* const* d_in, const int* in_sizes, int n_in,
                              void* d_out, int out_size)
{
    const float* x     = (const float*)d_in[0];
    const float* Wq    = (const float*)d_in[1];
    const float* Wk    = (const float*)d_in[2];
    const float* Wv    = (const float*)d_in[3];
    const float* proj  = (const float*)d_in[4];
    const float* Wpost = (const float*)d_in[5];
    const float* Wout  = (const float*)d_in[6];
    float* out = (float*)d_out;

    float *pQ, *pK, *pV, *pphiq, *pphik, *pkv, *pks;
    __half *pxhi, *pxlo, *pahi, *palo, *pwh;
    cudaGetSymbolAddress((void**)&pQ, g_Q);
    cudaGetSymbolAddress((void**)&pK, g_K);
    cudaGetSymbolAddress((void**)&pV, g_V);
    cudaGetSymbolAddress((void**)&pphiq, g_phiq);
    cudaGetSymbolAddress((void**)&pphik, g_phik);
    cudaGetSymbolAddress((void**)&pkv, g_kv);
    cudaGetSymbolAddress((void**)&pks, g_ks);
    cudaGetSymbolAddress((void**)&pxhi, g_xhi);
    cudaGetSymbolAddress((void**)&pxlo, g_xlo);
    cudaGetSymbolAddress((void**)&pahi, g_ahi);
    cudaGetSymbolAddress((void**)&palo, g_alo);
    cudaGetSymbolAddress((void**)&pwh, g_wh);

    static const size_t chunk_smem = (size_t)(5*64*PAD + 128) * sizeof(float);
    cudaFuncSetAttribute(chunk_out_kernel, cudaFuncAttributeMaxDynamicSharedMemorySize,
                         (int)chunk_smem);
    static const int gemm_smem = NSTAGE * BUFB;     // 92160 B
    cudaFuncSetAttribute(gemm_hmma_split, cudaFuncAttributeMaxDynamicSharedMemorySize, gemm_smem);

    convert_all<<<11264, 256>>>(x, Wq, Wk, Wv, pxhi, pxlo, pwh);
    w2_kernel<<<dim3(16, 16), 256>>>(Wout, Wpost, pwh + 3*DIM*DIM);

    dim3 gqkv(24, MROWS/128);
    gemm_hmma_split<<<gqkv, 256, gemm_smem>>>(pxhi, pxlo, pwh, pQ, pK, pV, DIM);

    feature_both<<<2*(ROWS/64), 256>>>(pQ, pK, proj, pphiq, pphik);

    dim3 gc(NCHUNK, NBH);
    chunk_local_kernel<<<gc, 256>>>(pphik, pV, pkv, pks);
    dim3 gp(16, NBH);
    prefix_kernel<<<gp, 256>>>(pkv, pks);
    chunk_out_kernel<<<gc, 256, chunk_smem>>>(pphiq, pphik, pV, pkv, pks, pahi, palo);

    dim3 gout(8, MROWS/128);
    gemm_hmma_split<<<gout, 256, gemm_smem>>>(pahi, palo, pwh + 3*DIM*DIM, out, out, out, DIM);
}

// round 16
// speedup vs baseline: 1.4359x; 1.0916x over previous
#include <cuda_runtime.h>
#include <cuda_fp16.h>
#include <math.h>
#include <cstdint>

// Problem constants
#define BATCH 4
#define SEQ   2048
#define DIM   1024
#define HEADS 16
#define DH    64
#define NF    64
#define NBH   (BATCH*HEADS)          // 64
#define ROWS  (NBH*SEQ)              // 131072 head-rows
#define MROWS (BATCH*SEQ)            // 8192 GEMM rows
#define CH    64                     // chunk length
#define NCHUNK (SEQ/CH)              // 32
#define PAD   68

// ---------------- device scratch ----------------
__device__ float g_V[ROWS*DH];
__device__ float g_phiq[ROWS*NF];
__device__ float g_phik[ROWS*NF];
__device__ float g_kv[NBH*NCHUNK*NF*DH];
__device__ float g_ks[NBH*NCHUNK*NF];
// fp16 split buffers
__device__ __half g_xhi[MROWS*DIM];
__device__ __half g_xlo[MROWS*DIM];
__device__ __half g_ahi[MROWS*DIM];
__device__ __half g_alo[MROWS*DIM];
__device__ __half g_wh[4*DIM*DIM];   // slots 0-2: Wq/Wk/Wv ; slot 3: W2 = fold(Wout, Wpost)
__device__ __half g_qhi[ROWS*DH];
__device__ __half g_qlo[ROWS*DH];
__device__ __half g_khi[ROWS*DH];
__device__ __half g_klo[ROWS*DH];
__device__ __half g_ph[NF*DH];       // dn-scaled proj, fp16 hi
__device__ __half g_pl[NF*DH];       // fp16 lo

// ================= helpers =================
__device__ __forceinline__ uint32_t smem_u32(const void* p) {
    uint32_t a;
    asm("{ .reg .u64 tmp; cvta.to.shared.u64 tmp, %1; cvt.u32.u64 %0, tmp; }" : "=r"(a) : "l"(p));
    return a;
}
__device__ __forceinline__ void ldm_x4(uint32_t* r, uint32_t addr) {
    asm volatile("ldmatrix.sync.aligned.m8n8.x4.shared.b16 {%0,%1,%2,%3}, [%4];"
        : "=r"(r[0]), "=r"(r[1]), "=r"(r[2]), "=r"(r[3]) : "r"(addr));
}
__device__ __forceinline__ void mma_f16(float* d, const uint32_t* a, const uint32_t* b) {
    asm volatile("mma.sync.aligned.m16n8k16.row.col.f32.f16.f16.f32 "
        "{%0,%1,%2,%3}, {%4,%5,%6,%7}, {%8,%9}, {%0,%1,%2,%3};"
        : "+f"(d[0]), "+f"(d[1]), "+f"(d[2]), "+f"(d[3])
        : "r"(a[0]), "r"(a[1]), "r"(a[2]), "r"(a[3]), "r"(b[0]), "r"(b[1]));
}
__device__ __forceinline__ void cp16(uint32_t dst, const void* src) {
    asm volatile("cp.async.cg.shared.global [%0], [%1], 16;" :: "r"(dst), "l"(src));
}
#define CP_COMMIT() asm volatile("cp.async.commit_group;" ::: "memory")
#define CP_WAIT(N)  asm volatile("cp.async.wait_group %0;" :: "n"(N) : "memory")

// ================= fused conversion: x split, Wq/Wk/Wv fp16, proj dn-scaled split =================
__global__ __launch_bounds__(256) void convert_all(
    const float* __restrict__ x,
    const float* __restrict__ Wq, const float* __restrict__ Wk,
    const float* __restrict__ Wv, const float* __restrict__ proj,
    __half* __restrict__ xhi, __half* __restrict__ xlo,
    __half* __restrict__ wh, __half* __restrict__ ph, __half* __restrict__ pl)
{
    const int b = blockIdx.x;
    if (b < 8192) {
        const int i = b * 256 + threadIdx.x;
        float4 v = ((const float4*)x)[i];
        __half h0 = __float2half(v.x), h1 = __float2half(v.y);
        __half h2 = __float2half(v.z), h3 = __float2half(v.w);
        __half2 p;
        p.x = h0; p.y = h1; ((__half2*)xhi)[2*i]   = p;
        p.x = h2; p.y = h3; ((__half2*)xhi)[2*i+1] = p;
        p.x = __float2half(v.x - __half2float(h0));
        p.y = __float2half(v.y - __half2float(h1));
        ((__half2*)xlo)[2*i] = p;
        p.x = __float2half(v.z - __half2float(h2));
        p.y = __float2half(v.w - __half2float(h3));
        ((__half2*)xlo)[2*i+1] = p;
    } else if (b < 11264) {
        const int wb = b - 8192;
        const int w = wb >> 10;          // 0..2
        const int r = wb & 1023;
        const float* src = (w == 0) ? Wq : (w == 1) ? Wk : Wv;
        __half* hi = wh + (size_t)w * DIM * DIM;
        const int i = r * 256 + threadIdx.x;
        float4 v = ((const float4*)src)[i];
        __half2 p;
        p.x = __float2half(v.x); p.y = __float2half(v.y);
        ((__half2*)hi)[2*i] = p;
        p.x = __float2half(v.z); p.y = __float2half(v.w);
        ((__half2*)hi)[2*i+1] = p;
    } else {
        // proj: 1024 float4 over 4 blocks; dn-scaled hi/lo split
        const int i = (b - 11264) * 256 + threadIdx.x;
        const float dn = 0.35355339059327373f;
        float4 v = ((const float4*)proj)[i];
        v.x *= dn; v.y *= dn; v.z *= dn; v.w *= dn;
        __half h0 = __float2half(v.x), h1 = __float2half(v.y);
        __half h2 = __float2half(v.z), h3 = __float2half(v.w);
        __half2 p;
        p.x = h0; p.y = h1; ((__half2*)ph)[2*i]   = p;
        p.x = h2; p.y = h3; ((__half2*)ph)[2*i+1] = p;
        p.x = __float2half(v.x - __half2float(h0));
        p.y = __float2half(v.y - __half2float(h1));
        ((__half2*)pl)[2*i] = p;
        p.x = __float2half(v.z - __half2float(h2));
        p.y = __float2half(v.w - __half2float(h3));
        ((__half2*)pl)[2*i+1] = p;
    }
}

// ================= W2 = per-head fold of Wout @ Wpost =================
__global__ __launch_bounds__(256) void w2_kernel(const float* __restrict__ Wout,
                                                 const float* __restrict__ Wpost,
                                                 __half* __restrict__ w2h)
{
    __shared__ float Wo[64*64];
    __shared__ float Wp[64*68];
    const int h = blockIdx.y;
    const int o0 = blockIdx.x * 64;
    const int t = threadIdx.x;

    for (int i = t; i < 4096; i += 256) {
        int r = i >> 6, e = i & 63;
        Wo[i] = Wout[(size_t)(o0 + r) * DIM + h * 64 + e];
        int e2 = i >> 6, c = i & 63;
        Wp[e2*68 + c] = Wpost[i];
    }
    __syncthreads();

    const int r0 = (t >> 4) * 4;
    const int c0 = (t & 15) * 4;
    float acc[4][4];
#pragma unroll
    for (int i = 0; i < 4; i++)
#pragma unroll
        for (int j = 0; j < 4; j++) acc[i][j] = 0.f;
#pragma unroll 8
    for (int e = 0; e < 64; e++) {
        float4 wp = *(const float4*)&Wp[e*68 + c0];
#pragma unroll
        for (int i = 0; i < 4; i++) {
            float a = Wo[(r0 + i)*64 + e];
            acc[i][0] += a * wp.x; acc[i][1] += a * wp.y;
            acc[i][2] += a * wp.z; acc[i][3] += a * wp.w;
        }
    }
#pragma unroll
    for (int i = 0; i < 4; i++) {
        __half2 p0, p1;
        p0.x = __float2half(acc[i][0]); p0.y = __float2half(acc[i][1]);
        p1.x = __float2half(acc[i][2]); p1.y = __float2half(acc[i][3]);
        __half* dst = w2h + (size_t)(o0 + r0 + i) * DIM + h * 64 + c0;
        *(__half2*)dst = p0;
        *(__half2*)(dst + 2) = p1;
    }
}

// ================= HMMA fp16 A-split GEMM =================
// mode 0 (QKV): which 0/1 -> fp16-split Q/K outputs; which 2 -> fp32 V.
// mode 1 (final): fp32 out.
#define TS 10240
#define BUFB (3*TS)
#define NSTAGE 3

__global__ __launch_bounds__(256, 2) void gemm_hmma_split(
    const __half* __restrict__ Ahi, const __half* __restrict__ Alo,
    const __half* __restrict__ Bh_all,
    __half* __restrict__ qhi, __half* __restrict__ qlo,
    __half* __restrict__ khi, __half* __restrict__ klo,
    float* __restrict__ Cf, int mode, int K)
{
    extern __shared__ char smx[];
    const int t = threadIdx.x;
    const int wid = t >> 5, lane = t & 31;
    const int wm = wid >> 2, wn = wid & 3;          // 2m x 4n, warp tile 64x32
    const int bm = blockIdx.y * 128;
    const int which = blockIdx.x >> 3;
    const int bn = (blockIdx.x & 7) * 128;
    const __half* Bh = Bh_all + (size_t)which * DIM * DIM;

    const uint32_t smb = smem_u32(smx);
    const __half* srcs[3] = {Ahi, Alo, Bh};

    float acc[4][4][4];
#pragma unroll
    for (int i = 0; i < 4; i++)
#pragma unroll
        for (int j = 0; j < 4; j++)
#pragma unroll
            for (int q = 0; q < 4; q++) acc[i][j][q] = 0.f;

    auto issue = [&](int s, int b) {
        const int k0 = s * 32;
#pragma unroll
        for (int q = 0; q < 6; q++) {
            const int tile = q >> 1;
            const int i = (q & 1) * 256 + t;
            const int r = i >> 2, ch = i & 3;
            const int rb = (tile < 2) ? bm : bn;
            cp16(smb + b * BUFB + tile * TS + r * 80 + ch * 16,
                 srcs[tile] + (size_t)(rb + r) * K + k0 + ch * 8);
        }
        CP_COMMIT();
    };

    auto compute = [&](int b) {
        const uint32_t Ahb = smb + b * BUFB;
        const uint32_t Alb = Ahb + TS;
        const uint32_t Bhb = Ahb + 2 * TS;
        const int lrA = lane & 15, kbA = lane >> 4;
        const int nrB = (lane & 7) + ((lane >> 4) << 3);
        const int kbB = (lane >> 3) & 1;
#pragma unroll
        for (int ks = 0; ks < 2; ks++) {
            uint32_t bhf[4][2];
#pragma unroll
            for (int np = 0; np < 2; np++) {
                uint32_t off = (uint32_t)((wn * 32 + np * 16 + nrB) * 80 + ks * 32 + kbB * 16);
                uint32_t tmp[4];
                ldm_x4(tmp, Bhb + off);
                bhf[2*np][0] = tmp[0]; bhf[2*np][1] = tmp[1];
                bhf[2*np+1][0] = tmp[2]; bhf[2*np+1][1] = tmp[3];
            }
#pragma unroll
            for (int ma = 0; ma < 4; ma++) {
                uint32_t ah[4], al[4];
                uint32_t off = (uint32_t)((wm * 64 + ma * 16 + lrA) * 80 + ks * 32 + kbA * 16);
                ldm_x4(ah, Ahb + off);
                ldm_x4(al, Alb + off);
#pragma unroll
                for (int na = 0; na < 4; na++) {
                    mma_f16(acc[ma][na], ah, bhf[na]);
                    mma_f16(acc[ma][na], al, bhf[na]);
                }
            }
        }
    };

    const int S = K / 32;
    issue(0, 0);
    issue(1, 1);
    for (int s = 0; s < S; s++) {
        if (s + 1 < S) { CP_WAIT(1); } else { CP_WAIT(0); }
        __syncthreads();
        if (s + 2 < S) issue(s + 2, (s + 2) % NSTAGE);
        compute(s % NSTAGE);
    }

    const int g = lane >> 2, tig = lane & 3;
    if (mode == 0 && which < 2) {
        __half* H = which ? khi : qhi;
        __half* L = which ? klo : qlo;
#pragma unroll
        for (int ma = 0; ma < 4; ma++) {
            const int r0 = bm + wm * 64 + ma * 16 + g;
#pragma unroll
            for (int na = 0; na < 4; na++) {
                const int c = bn + wn * 32 + na * 8 + tig * 2;
#pragma unroll
                for (int m2 = 0; m2 < 2; m2++) {
                    float f0 = acc[ma][na][2*m2], f1 = acc[ma][na][2*m2+1];
                    __half h0 = __float2half(f0), h1 = __float2half(f1);
                    __half2 hh, ll;
                    hh.x = h0; hh.y = h1;
                    ll.x = __float2half(f0 - __half2float(h0));
                    ll.y = __float2half(f1 - __half2float(h1));
                    *(__half2*)(H + (size_t)(r0 + 8*m2) * DIM + c) = hh;
                    *(__half2*)(L + (size_t)(r0 + 8*m2) * DIM + c) = ll;
                }
            }
        }
    } else {
#pragma unroll
        for (int ma = 0; ma < 4; ma++) {
            const int r0 = bm + wm * 64 + ma * 16 + g;
#pragma unroll
            for (int na = 0; na < 4; na++) {
                const int c = bn + wn * 32 + na * 8 + tig * 2;
                *(float2*)(Cf + (size_t)r0 * DIM + c)       = make_float2(acc[ma][na][0], acc[ma][na][1]);
                *(float2*)(Cf + (size_t)(r0 + 8) * DIM + c) = make_float2(acc[ma][na][2], acc[ma][na][3]);
            }
        }
    }
}

// ================= feature map via HMMA (3-product fp16 split) =================
#define FSTR 72    // fp16 row stride (144 B)

__global__ __launch_bounds__(128) void feature_mma(
    const __half* __restrict__ qh, const __half* __restrict__ ql,
    const __half* __restrict__ kh, const __half* __restrict__ kl,
    const __half* __restrict__ ph, const __half* __restrict__ pl,
    float* __restrict__ phiq, float* __restrict__ phik)
{
    __shared__ __half Ah[64*FSTR], Al[64*FSTR], Bh[64*FSTR], Bl[64*FSTR];
    __shared__ float sqs[64];
    const int t = threadIdx.x;
    const int lane = t & 31, wr = t >> 5;
    const int nb = ROWS / 64;
    const int isq = (blockIdx.x < nb) ? 1 : 0;
    const int blk = isq ? blockIdx.x : blockIdx.x - nb;
    const __half* Xh = isq ? qh : kh;
    const __half* Xl = isq ? ql : kl;
    float* phi = isq ? phiq : phik;
    const size_t base = (size_t)blk * 4096;

    for (int i = t; i < 512; i += 128) {
        int r = i >> 3, ch = i & 7;
        *(float4*)&Ah[r*FSTR + ch*8] = *(const float4*)(Xh + base + r*64 + ch*8);
        *(float4*)&Al[r*FSTR + ch*8] = *(const float4*)(Xl + base + r*64 + ch*8);
        *(float4*)&Bh[r*FSTR + ch*8] = *(const float4*)(ph + r*64 + ch*8);
        *(float4*)&Bl[r*FSTR + ch*8] = *(const float4*)(pl + r*64 + ch*8);
    }
    __syncthreads();

    // ||q||^2 per row (fp32 from hi+lo); rows t>>1, halves (t&1)*32
    {
        const int row = t >> 1, h0 = (t & 1) * 32;
        float s = 0.f;
#pragma unroll 8
        for (int d = 0; d < 32; d += 2) {
            __half2 a = *(__half2*)&Ah[row*FSTR + h0 + d];
            __half2 b = *(__half2*)&Al[row*FSTR + h0 + d];
            float q0 = __half2float(a.x) + __half2float(b.x);
            float q1 = __half2float(a.y) + __half2float(b.y);
            s += q0*q0 + q1*q1;
        }
        s += __shfl_xor_sync(0xffffffffu, s, 1);
        if (!(t & 1)) sqs[row] = s;
        __syncwarp();
    }

    // MMA: logits[64 rows x 64 f] = (Ah+Al) @ (Bh+Bl)^T, drop lo*lo
    float acc[8][4];
#pragma unroll
    for (int i = 0; i < 8; i++)
#pragma unroll
        for (int j = 0; j < 4; j++) acc[i][j] = 0.f;

    const uint32_t As = smem_u32(Ah), Als = smem_u32(Al);
    const uint32_t Bs = smem_u32(Bh), Bls = smem_u32(Bl);
    const int lrA = lane & 15, kbA = lane >> 4;
    const int nrB = (lane & 7) + ((lane >> 4) << 3);
    const int kbB = (lane >> 3) & 1;
#pragma unroll
    for (int ks = 0; ks < 4; ks++) {
        uint32_t ah[4], al[4];
        const uint32_t aoff = (uint32_t)((wr*16 + lrA) * (FSTR*2) + ks*32 + kbA*16);
        ldm_x4(ah, As + aoff);
        ldm_x4(al, Als + aoff);
#pragma unroll
        for (int nt2 = 0; nt2 < 4; nt2++) {
            const uint32_t boff = (uint32_t)((nt2*16 + nrB) * (FSTR*2) + ks*32 + kbB*16);
            uint32_t bh4[4], bl4[4];
            ldm_x4(bh4, Bs + boff);
            ldm_x4(bl4, Bls + boff);
            uint32_t b0h[2] = {bh4[0], bh4[1]}, b1h[2] = {bh4[2], bh4[3]};
            uint32_t b0l[2] = {bl4[0], bl4[1]}, b1l[2] = {bl4[2], bl4[3]};
            mma_f16(acc[2*nt2],   ah, b0h);
            mma_f16(acc[2*nt2],   ah, b0l);
            mma_f16(acc[2*nt2],   al, b0h);
            mma_f16(acc[2*nt2+1], ah, b1h);
            mma_f16(acc[2*nt2+1], ah, b1l);
            mma_f16(acc[2*nt2+1], al, b1h);
        }
    }

    // epilogue: rows wr*16 + g (+8); cols nt*8 + q*2
    const int g = lane >> 2, q = lane & 3;
#pragma unroll
    for (int half = 0; half < 2; half++) {
        const int row = wr*16 + g + half*8;
        float v[8][2];
#pragma unroll
        for (int nt = 0; nt < 8; nt++) {
            v[nt][0] = acc[nt][2*half];
            v[nt][1] = acc[nt][2*half + 1];
        }
        float sub = sqs[row] * (1.0f / 128.0f);
        if (isq) {
            float mx = v[0][0];
#pragma unroll
            for (int nt = 0; nt < 8; nt++) { mx = fmaxf(mx, v[nt][0]); mx = fmaxf(mx, v[nt][1]); }
            mx = fmaxf(mx, __shfl_xor_sync(0xffffffffu, mx, 1));
            mx = fmaxf(mx, __shfl_xor_sync(0xffffffffu, mx, 2));
            sub += mx;
        }
        float* dst = phi + base + (size_t)row * 64;
#pragma unroll
        for (int nt = 0; nt < 8; nt++) {
            float2 o;
            o.x = 0.125f * (__expf(v[nt][0] - sub) + 1e-4f);
            o.y = 0.125f * (__expf(v[nt][1] - sub) + 1e-4f);
            *(float2*)(dst + nt*8 + q*2) = o;
        }
    }
}

// ================= chunk_local =================
__global__ __launch_bounds__(256) void chunk_local_kernel(const float* __restrict__ phiK,
                                                          const float* __restrict__ V,
                                                          float* __restrict__ kvloc,
                                                          float* __restrict__ kloc)
{
    __shared__ float ks[64*PAD];
    __shared__ float vs[64*PAD];
    const int t = threadIdx.x;
    const int chunk = blockIdx.x, bh = blockIdx.y;
    const size_t base = ((size_t)bh * SEQ + chunk * CH) * 64;

    for (int i = t; i < 1024; i += 256) {
        int r = i >> 4, c4 = (i & 15) << 2;
        *(float4*)&ks[r*PAD + c4] = *(const float4*)(phiK + base + (size_t)r*64 + c4);
        *(float4*)&vs[r*PAD + c4] = *(const float4*)(V    + base + (size_t)r*64 + c4);
    }
    __syncthreads();

    const int f0 = (t >> 4) << 2;
    const int c0 = (t & 15) << 2;
    float acc[4][4], kl[4];
#pragma unroll
    for (int i = 0; i < 4; i++) { kl[i] = 0.f;
#pragma unroll
        for (int j = 0; j < 4; j++) acc[i][j] = 0.f; }

#pragma unroll 8
    for (int r = 0; r < 64; r++) {
        float4 k4 = *(const float4*)&ks[r*PAD + f0];
        float4 v4 = *(const float4*)&vs[r*PAD + c0];
        float kv[4] = {k4.x, k4.y, k4.z, k4.w};
        float vv[4] = {v4.x, v4.y, v4.z, v4.w};
#pragma unroll
        for (int i = 0; i < 4; i++) {
            kl[i] += kv[i];
#pragma unroll
            for (int j = 0; j < 4; j++) acc[i][j] += kv[i] * vv[j];
        }
    }
    const size_t ob = ((size_t)bh * NCHUNK + chunk) * (64*64);
#pragma unroll
    for (int i = 0; i < 4; i++)
        *(float4*)&kvloc[ob + (size_t)(f0+i)*64 + c0] =
            make_float4(acc[i][0], acc[i][1], acc[i][2], acc[i][3]);
    if ((t & 15) == 0) {
        const size_t kb = ((size_t)bh * NCHUNK + chunk) * 64 + f0;
#pragma unroll
        for (int i = 0; i < 4; i++) kloc[kb + i] = kl[i];
    }
}

// ================= prefix =================
__global__ __launch_bounds__(256) void prefix_kernel(float* __restrict__ kvloc,
                                                     float* __restrict__ kloc)
{
    const int g = blockIdx.x, bh = blockIdx.y;
    const int t = threadIdx.x;
    const int e = g * 256 + t;
    float run = 0.f;
    for (int c = 0; c < NCHUNK; c++) {
        const size_t idx = ((size_t)bh * NCHUNK + c) * 4096 + e;
        float v = kvloc[idx];
        kvloc[idx] = run;
        run += v;
    }
    if (g == 0 && t < 64) {
        float rk = 0.f;
        for (int c = 0; c < NCHUNK; c++) {
            const size_t b = ((size_t)bh * NCHUNK + c) * 64 + t;
            float v = kloc[b];
            kloc[b] = rk;
            rk += v;
        }
    }
}

// ================= chunk_out =================
__global__ __launch_bounds__(256) void chunk_out_kernel(const float* __restrict__ phiQ,
                                                        const float* __restrict__ phiK,
                                                        const float* __restrict__ Vg,
                                                        const float* __restrict__ KVp,
                                                        const float* __restrict__ Kp,
                                                        __half* __restrict__ ahi,
                                                        __half* __restrict__ alo)
{
    extern __shared__ float sm[];
    float* QsT = sm;
    float* KsT = QsT + 64*PAD;
    float* Vs  = KsT + 64*PAD;
    float* KVs = Vs  + 64*PAD;
    float* Ss  = KVs + 64*PAD;
    float* den = Ss  + 64*PAD;
    float* kps = den + 64;

    const int t = threadIdx.x;
    const int chunk = blockIdx.x, bh = blockIdx.y;
    const size_t base   = ((size_t)bh * SEQ + chunk * CH) * 64;
    const size_t kvbase = ((size_t)bh * NCHUNK + chunk) * 4096;

    for (int i = t; i < 1024; i += 256) {
        int r = i >> 4, c4 = (i & 15) << 2;
        float4 q = *(const float4*)(phiQ + base + (size_t)r*64 + c4);
        float4 k = *(const float4*)(phiK + base + (size_t)r*64 + c4);
        QsT[(c4+0)*PAD + r] = q.x; QsT[(c4+1)*PAD + r] = q.y;
        QsT[(c4+2)*PAD + r] = q.z; QsT[(c4+3)*PAD + r] = q.w;
        KsT[(c4+0)*PAD + r] = k.x; KsT[(c4+1)*PAD + r] = k.y;
        KsT[(c4+2)*PAD + r] = k.z; KsT[(c4+3)*PAD + r] = k.w;
        *(float4*)&Vs [r*PAD + c4] = *(const float4*)(Vg  + base   + (size_t)r*64 + c4);
        *(float4*)&KVs[r*PAD + c4] = *(const float4*)(KVp + kvbase + (size_t)r*64 + c4);
    }
    if (t < 64) kps[t] = Kp[((size_t)bh * NCHUNK + chunk) * 64 + t];
    __syncthreads();

    const int r0 = (t >> 4) << 2;
    const int c0 = (t & 15) << 2;

    // ---- Phase S ----
    float sacc[4][4], kq[4];
#pragma unroll
    for (int i = 0; i < 4; i++) { kq[i] = 0.f;
#pragma unroll
        for (int j = 0; j < 4; j++) sacc[i][j] = 0.f; }
#pragma unroll 8
    for (int d = 0; d < 64; d++) {
        float4 q4 = *(const float4*)&QsT[d*PAD + r0];
        float4 k4 = *(const float4*)&KsT[d*PAD + c0];
        float kp = kps[d];
        float qv[4] = {q4.x, q4.y, q4.z, q4.w};
        float kv[4] = {k4.x, k4.y, k4.z, k4.w};
#pragma unroll
        for (int i = 0; i < 4; i++) {
            kq[i] += qv[i] * kp;
#pragma unroll
            for (int j = 0; j < 4; j++) sacc[i][j] += qv[i] * kv[j];
        }
    }
    float rs[4];
#pragma unroll
    for (int i = 0; i < 4; i++) {
        const int r = r0 + i;
        float m0 = (c0+0 <= r) ? sacc[i][0] : 0.f;
        float m1 = (c0+1 <= r) ? sacc[i][1] : 0.f;
        float m2 = (c0+2 <= r) ? sacc[i][2] : 0.f;
        float m3 = (c0+3 <= r) ? sacc[i][3] : 0.f;
        *(float4*)&Ss[r*PAD + c0] = make_float4(m0, m1, m2, m3);
        rs[i] = m0 + m1 + m2 + m3;
    }
#pragma unroll
    for (int o = 8; o >= 1; o >>= 1)
#pragma unroll
        for (int i = 0; i < 4; i++) rs[i] += __shfl_xor_sync(0xffffffffu, rs[i], o);
    if ((t & 15) == 0) {
#pragma unroll
        for (int i = 0; i < 4; i++) den[r0 + i] = fmaxf(rs[i] + kq[i], 1e-6f);
    }
    __syncthreads();

    // ---- Phase O: G = (S V + Q KVprev) / den ----
    float oacc[4][4];
#pragma unroll
    for (int i = 0; i < 4; i++)
#pragma unroll
        for (int j = 0; j < 4; j++) oacc[i][j] = 0.f;
#pragma unroll 4
    for (int j0 = 0; j0 < 64; j0 += 4) {
        float4 s4[4], v4[4];
#pragma unroll
        for (int i = 0; i < 4; i++)  s4[i]  = *(const float4*)&Ss[(r0+i)*PAD + j0];
#pragma unroll
        for (int jj = 0; jj < 4; jj++) v4[jj] = *(const float4*)&Vs[(j0+jj)*PAD + c0];
#pragma unroll
        for (int i = 0; i < 4; i++) {
            float sv[4] = {s4[i].x, s4[i].y, s4[i].z, s4[i].w};
#pragma unroll
            for (int jj = 0; jj < 4; jj++) {
                oacc[i][0] += sv[jj] * (&v4[jj].x)[0];
                oacc[i][1] += sv[jj] * (&v4[jj].x)[1];
                oacc[i][2] += sv[jj] * (&v4[jj].x)[2];
                oacc[i][3] += sv[jj] * (&v4[jj].x)[3];
            }
        }
    }
#pragma unroll 4
    for (int f0 = 0; f0 < 64; f0 += 4) {
        float4 q4[4], kv4[4];
#pragma unroll
        for (int jj = 0; jj < 4; jj++) {
            q4[jj]  = *(const float4*)&QsT[(f0+jj)*PAD + r0];
            kv4[jj] = *(const float4*)&KVs[(f0+jj)*PAD + c0];
        }
#pragma unroll
        for (int jj = 0; jj < 4; jj++) {
            float qv[4] = {q4[jj].x, q4[jj].y, q4[jj].z, q4[jj].w};
#pragma unroll
            for (int i = 0; i < 4; i++) {
                oacc[i][0] += qv[i] * (&kv4[jj].x)[0];
                oacc[i][1] += qv[i] * (&kv4[jj].x)[1];
                oacc[i][2] += qv[i] * (&kv4[jj].x)[2];
                oacc[i][3] += qv[i] * (&kv4[jj].x)[3];
            }
        }
    }

    // ---- store G with head-transpose + fp16 split ----
    const int bi = bh >> 4, hi2 = bh & 15;
#pragma unroll
    for (int i = 0; i < 4; i++) {
        const float inv = 1.0f / den[r0 + i];
        const int si = chunk * CH + r0 + i;
        const size_t ob = ((size_t)bi * SEQ + si) * DIM + hi2 * 64 + c0;
        __half2 hp[2], lp[2];
#pragma unroll
        for (int j = 0; j < 2; j++) {
            float fa = oacc[i][2*j] * inv, fb = oacc[i][2*j+1] * inv;
            __half ha = __float2half(fa);
            __half hb = __float2half(fb);
            hp[j].x = ha; hp[j].y = hb;
            lp[j].x = __float2half(fa - __half2float(ha));
            lp[j].y = __float2half(fb - __half2float(hb));
        }
        *(float2*)(ahi + ob) = *(float2*)hp;
        *(float2*)(alo + ob) = *(float2*)lp;
    }
}

// ================= launch =================
extern "C" void kernel_launch(void* const* d_in, const int* in_sizes, int n_in,
                              void* d_out, int out_size)
{
    const float* x     = (const float*)d_in[0];
    const float* Wq    = (const float*)d_in[1];
    const float* Wk    = (const float*)d_in[2];
    const float* Wv    = (const float*)d_in[3];
    const float* proj  = (const float*)d_in[4];
    const float* Wpost = (const float*)d_in[5];
    const float* Wout  = (const float*)d_in[6];
    float* out = (float*)d_out;

    float *pV, *pphiq, *pphik, *pkv, *pks;
    __half *pxhi, *pxlo, *pahi, *palo, *pwh, *pqhi, *pqlo, *pkhi, *pklo, *pph, *ppl;
    cudaGetSymbolAddress((void**)&pV, g_V);
    cudaGetSymbolAddress((void**)&pphiq, g_phiq);
    cudaGetSymbolAddress((void**)&pphik, g_phik);
    cudaGetSymbolAddress((void**)&pkv, g_kv);
    cudaGetSymbolAddress((void**)&pks, g_ks);
    cudaGetSymbolAddress((void**)&pxhi, g_xhi);
    cudaGetSymbolAddress((void**)&pxlo, g_xlo);
    cudaGetSymbolAddress((void**)&pahi, g_ahi);
    cudaGetSymbolAddress((void**)&palo, g_alo);
    cudaGetSymbolAddress((void**)&pwh, g_wh);
    cudaGetSymbolAddress((void**)&pqhi, g_qhi);
    cudaGetSymbolAddress((void**)&pqlo, g_qlo);
    cudaGetSymbolAddress((void**)&pkhi, g_khi);
    cudaGetSymbolAddress((void**)&pklo, g_klo);
    cudaGetSymbolAddress((void**)&pph, g_ph);
    cudaGetSymbolAddress((void**)&ppl, g_pl);

    static const size_t chunk_smem = (size_t)(5*64*PAD + 128) * sizeof(float);
    cudaFuncSetAttribute(chunk_out_kernel, cudaFuncAttributeMaxDynamicSharedMemorySize,
                         (int)chunk_smem);
    static const int gemm_smem = NSTAGE * BUFB;     // 92160 B
    cudaFuncSetAttribute(gemm_hmma_split, cudaFuncAttributeMaxDynamicSharedMemorySize, gemm_smem);

    convert_all<<<11268, 256>>>(x, Wq, Wk, Wv, proj, pxhi, pxlo, pwh, pph, ppl);
    w2_kernel<<<dim3(16, 16), 256>>>(Wout, Wpost, pwh + 3*DIM*DIM);

    dim3 gqkv(24, MROWS/128);
    gemm_hmma_split<<<gqkv, 256, gemm_smem>>>(pxhi, pxlo, pwh,
                                              pqhi, pqlo, pkhi, pklo, pV, 0, DIM);

    feature_mma<<<2*(ROWS/64), 128>>>(pqhi, pqlo, pkhi, pklo, pph, ppl, pphiq, pphik);

    dim3 gc(NCHUNK, NBH);
    chunk_local_kernel<<<gc, 256>>>(pphik, pV, pkv, pks);
    dim3 gp(16, NBH);
    prefix_kernel<<<gp, 256>>>(pkv, pks);
    chunk_out_kernel<<<gc, 256, chunk_smem>>>(pphiq, pphik, pV, pkv, pks, pahi, palo);

    dim3 gout(8, MROWS/128);
    gemm_hmma_split<<<gout, 256, gemm_smem>>>(pahi, palo, pwh + 3*DIM*DIM,
                                              (__half*)0, (__half*)0, (__half*)0, (__half*)0,
                                              out, 1, DIM);
}

// round 17
// speedup vs baseline: 1.4371x; 1.0009x over previous
#include <cuda_runtime.h>
#include <cuda_fp16.h>
#include <math.h>
#include <cstdint>

// Problem constants
#define BATCH 4
#define SEQ   2048
#define DIM   1024
#define HEADS 16
#define DH    64
#define NF    64
#define NBH   (BATCH*HEADS)          // 64
#define ROWS  (NBH*SEQ)              // 131072 head-rows
#define MROWS (BATCH*SEQ)            // 8192 GEMM rows
#define CH    64                     // chunk length
#define NCHUNK (SEQ/CH)              // 32
#define PAD   68

// ---------------- device scratch ----------------
__device__ float g_V[ROWS*DH];
__device__ float g_phiq[ROWS*NF];
__device__ float g_phik[ROWS*NF];
__device__ float g_kv[NBH*NCHUNK*NF*DH];
__device__ float g_ks[NBH*NCHUNK*NF];
// fp16 split buffers
__device__ __half g_xhi[MROWS*DIM];
__device__ __half g_xlo[MROWS*DIM];
__device__ __half g_ahi[MROWS*DIM];
__device__ __half g_wh[4*DIM*DIM];   // slots 0-2: Wq/Wk/Wv ; slot 3: W2 = fold(Wout, Wpost)
__device__ __half g_qhi[ROWS*DH];
__device__ __half g_qlo[ROWS*DH];
__device__ __half g_khi[ROWS*DH];
__device__ __half g_klo[ROWS*DH];
__device__ __half g_ph[NF*DH];       // dn-scaled proj, fp16 hi
__device__ __half g_pl[NF*DH];       // fp16 lo

// ================= helpers =================
__device__ __forceinline__ uint32_t smem_u32(const void* p) {
    uint32_t a;
    asm("{ .reg .u64 tmp; cvta.to.shared.u64 tmp, %1; cvt.u32.u64 %0, tmp; }" : "=r"(a) : "l"(p));
    return a;
}
__device__ __forceinline__ void ldm_x4(uint32_t* r, uint32_t addr) {
    asm volatile("ldmatrix.sync.aligned.m8n8.x4.shared.b16 {%0,%1,%2,%3}, [%4];"
        : "=r"(r[0]), "=r"(r[1]), "=r"(r[2]), "=r"(r[3]) : "r"(addr));
}
__device__ __forceinline__ void mma_f16(float* d, const uint32_t* a, const uint32_t* b) {
    asm volatile("mma.sync.aligned.m16n8k16.row.col.f32.f16.f16.f32 "
        "{%0,%1,%2,%3}, {%4,%5,%6,%7}, {%8,%9}, {%0,%1,%2,%3};"
        : "+f"(d[0]), "+f"(d[1]), "+f"(d[2]), "+f"(d[3])
        : "r"(a[0]), "r"(a[1]), "r"(a[2]), "r"(a[3]), "r"(b[0]), "r"(b[1]));
}
__device__ __forceinline__ void cp16(uint32_t dst, const void* src) {
    asm volatile("cp.async.cg.shared.global [%0], [%1], 16;" :: "r"(dst), "l"(src));
}
#define CP_COMMIT() asm volatile("cp.async.commit_group;" ::: "memory")
#define CP_WAIT(N)  asm volatile("cp.async.wait_group %0;" :: "n"(N) : "memory")

// ================= fused conversion: x split, Wq/Wk/Wv fp16, proj dn-scaled split =================
__global__ __launch_bounds__(256) void convert_all(
    const float* __restrict__ x,
    const float* __restrict__ Wq, const float* __restrict__ Wk,
    const float* __restrict__ Wv, const float* __restrict__ proj,
    __half* __restrict__ xhi, __half* __restrict__ xlo,
    __half* __restrict__ wh, __half* __restrict__ ph, __half* __restrict__ pl)
{
    const int b = blockIdx.x;
    if (b < 8192) {
        const int i = b * 256 + threadIdx.x;
        float4 v = ((const float4*)x)[i];
        __half h0 = __float2half(v.x), h1 = __float2half(v.y);
        __half h2 = __float2half(v.z), h3 = __float2half(v.w);
        __half2 p;
        p.x = h0; p.y = h1; ((__half2*)xhi)[2*i]   = p;
        p.x = h2; p.y = h3; ((__half2*)xhi)[2*i+1] = p;
        p.x = __float2half(v.x - __half2float(h0));
        p.y = __float2half(v.y - __half2float(h1));
        ((__half2*)xlo)[2*i] = p;
        p.x = __float2half(v.z - __half2float(h2));
        p.y = __float2half(v.w - __half2float(h3));
        ((__half2*)xlo)[2*i+1] = p;
    } else if (b < 11264) {
        const int wb = b - 8192;
        const int w = wb >> 10;          // 0..2
        const int r = wb & 1023;
        const float* src = (w == 0) ? Wq : (w == 1) ? Wk : Wv;
        __half* hi = wh + (size_t)w * DIM * DIM;
        const int i = r * 256 + threadIdx.x;
        float4 v = ((const float4*)src)[i];
        __half2 p;
        p.x = __float2half(v.x); p.y = __float2half(v.y);
        ((__half2*)hi)[2*i] = p;
        p.x = __float2half(v.z); p.y = __float2half(v.w);
        ((__half2*)hi)[2*i+1] = p;
    } else {
        // proj: 1024 float4 over 4 blocks; dn-scaled hi/lo split
        const int i = (b - 11264) * 256 + threadIdx.x;
        const float dn = 0.35355339059327373f;
        float4 v = ((const float4*)proj)[i];
        v.x *= dn; v.y *= dn; v.z *= dn; v.w *= dn;
        __half h0 = __float2half(v.x), h1 = __float2half(v.y);
        __half h2 = __float2half(v.z), h3 = __float2half(v.w);
        __half2 p;
        p.x = h0; p.y = h1; ((__half2*)ph)[2*i]   = p;
        p.x = h2; p.y = h3; ((__half2*)ph)[2*i+1] = p;
        p.x = __float2half(v.x - __half2float(h0));
        p.y = __float2half(v.y - __half2float(h1));
        ((__half2*)pl)[2*i] = p;
        p.x = __float2half(v.z - __half2float(h2));
        p.y = __float2half(v.w - __half2float(h3));
        ((__half2*)pl)[2*i+1] = p;
    }
}

// ================= W2 = per-head fold of Wout @ Wpost =================
__global__ __launch_bounds__(256) void w2_kernel(const float* __restrict__ Wout,
                                                 const float* __restrict__ Wpost,
                                                 __half* __restrict__ w2h)
{
    __shared__ float Wo[64*64];
    __shared__ float Wp[64*68];
    const int h = blockIdx.y;
    const int o0 = blockIdx.x * 64;
    const int t = threadIdx.x;

    for (int i = t; i < 4096; i += 256) {
        int r = i >> 6, e = i & 63;
        Wo[i] = Wout[(size_t)(o0 + r) * DIM + h * 64 + e];
        int e2 = i >> 6, c = i & 63;
        Wp[e2*68 + c] = Wpost[i];
    }
    __syncthreads();

    const int r0 = (t >> 4) * 4;
    const int c0 = (t & 15) * 4;
    float acc[4][4];
#pragma unroll
    for (int i = 0; i < 4; i++)
#pragma unroll
        for (int j = 0; j < 4; j++) acc[i][j] = 0.f;
#pragma unroll 8
    for (int e = 0; e < 64; e++) {
        float4 wp = *(const float4*)&Wp[e*68 + c0];
#pragma unroll
        for (int i = 0; i < 4; i++) {
            float a = Wo[(r0 + i)*64 + e];
            acc[i][0] += a * wp.x; acc[i][1] += a * wp.y;
            acc[i][2] += a * wp.z; acc[i][3] += a * wp.w;
        }
    }
#pragma unroll
    for (int i = 0; i < 4; i++) {
        __half2 p0, p1;
        p0.x = __float2half(acc[i][0]); p0.y = __float2half(acc[i][1]);
        p1.x = __float2half(acc[i][2]); p1.y = __float2half(acc[i][3]);
        __half* dst = w2h + (size_t)(o0 + r0 + i) * DIM + h * 64 + c0;
        *(__half2*)dst = p0;
        *(__half2*)(dst + 2) = p1;
    }
}

// ================= HMMA fp16 A-split GEMM =================
// mode 0 (QKV): which 0/1 -> fp16-split Q/K outputs; which 2 -> fp32 V.  nprod=2.
// mode 1 (final): fp32 out, nprod=1 (single A product, Alo unused).
#define TS 10240
#define BUFB (3*TS)
#define NSTAGE 3

__global__ __launch_bounds__(256, 2) void gemm_hmma_split(
    const __half* __restrict__ Ahi, const __half* __restrict__ Alo,
    const __half* __restrict__ Bh_all,
    __half* __restrict__ qhi, __half* __restrict__ qlo,
    __half* __restrict__ khi, __half* __restrict__ klo,
    float* __restrict__ Cf, int mode, int nprod, int K)
{
    extern __shared__ char smx[];
    const int t = threadIdx.x;
    const int wid = t >> 5, lane = t & 31;
    const int wm = wid >> 2, wn = wid & 3;          // 2m x 4n, warp tile 64x32
    const int bm = blockIdx.y * 128;
    const int which = blockIdx.x >> 3;
    const int bn = (blockIdx.x & 7) * 128;
    const __half* Bh = Bh_all + (size_t)which * DIM * DIM;

    const uint32_t smb = smem_u32(smx);
    const __half* srcs[3] = {Ahi, Alo, Bh};

    float acc[4][4][4];
#pragma unroll
    for (int i = 0; i < 4; i++)
#pragma unroll
        for (int j = 0; j < 4; j++)
#pragma unroll
            for (int q = 0; q < 4; q++) acc[i][j][q] = 0.f;

    auto issue = [&](int s, int b) {
        const int k0 = s * 32;
#pragma unroll
        for (int q = 0; q < 6; q++) {
            const int tile = q >> 1;
            if (tile == 1 && nprod == 1) continue;   // skip Alo loads in single-product mode
            const int i = (q & 1) * 256 + t;
            const int r = i >> 2, ch = i & 3;
            const int rb = (tile < 2) ? bm : bn;
            cp16(smb + b * BUFB + tile * TS + r * 80 + ch * 16,
                 srcs[tile] + (size_t)(rb + r) * K + k0 + ch * 8);
        }
        CP_COMMIT();
    };

    auto compute = [&](int b) {
        const uint32_t Ahb = smb + b * BUFB;
        const uint32_t Alb = Ahb + TS;
        const uint32_t Bhb = Ahb + 2 * TS;
        const int lrA = lane & 15, kbA = lane >> 4;
        const int nrB = (lane & 7) + ((lane >> 4) << 3);
        const int kbB = (lane >> 3) & 1;
#pragma unroll
        for (int ks = 0; ks < 2; ks++) {
            uint32_t bhf[4][2];
#pragma unroll
            for (int np = 0; np < 2; np++) {
                uint32_t off = (uint32_t)((wn * 32 + np * 16 + nrB) * 80 + ks * 32 + kbB * 16);
                uint32_t tmp[4];
                ldm_x4(tmp, Bhb + off);
                bhf[2*np][0] = tmp[0]; bhf[2*np][1] = tmp[1];
                bhf[2*np+1][0] = tmp[2]; bhf[2*np+1][1] = tmp[3];
            }
#pragma unroll
            for (int ma = 0; ma < 4; ma++) {
                uint32_t ah[4], al[4];
                uint32_t off = (uint32_t)((wm * 64 + ma * 16 + lrA) * 80 + ks * 32 + kbA * 16);
                ldm_x4(ah, Ahb + off);
                if (nprod == 2) ldm_x4(al, Alb + off);
#pragma unroll
                for (int na = 0; na < 4; na++) {
                    mma_f16(acc[ma][na], ah, bhf[na]);
                    if (nprod == 2) mma_f16(acc[ma][na], al, bhf[na]);
                }
            }
        }
    };

    const int S = K / 32;
    issue(0, 0);
    issue(1, 1);
    for (int s = 0; s < S; s++) {
        if (s + 1 < S) { CP_WAIT(1); } else { CP_WAIT(0); }
        __syncthreads();
        if (s + 2 < S) issue(s + 2, (s + 2) % NSTAGE);
        compute(s % NSTAGE);
    }

    const int g = lane >> 2, tig = lane & 3;
    if (mode == 0 && which < 2) {
        __half* H = which ? khi : qhi;
        __half* L = which ? klo : qlo;
#pragma unroll
        for (int ma = 0; ma < 4; ma++) {
            const int r0 = bm + wm * 64 + ma * 16 + g;
#pragma unroll
            for (int na = 0; na < 4; na++) {
                const int c = bn + wn * 32 + na * 8 + tig * 2;
#pragma unroll
                for (int m2 = 0; m2 < 2; m2++) {
                    float f0 = acc[ma][na][2*m2], f1 = acc[ma][na][2*m2+1];
                    __half h0 = __float2half(f0), h1 = __float2half(f1);
                    __half2 hh, ll;
                    hh.x = h0; hh.y = h1;
                    ll.x = __float2half(f0 - __half2float(h0));
                    ll.y = __float2half(f1 - __half2float(h1));
                    *(__half2*)(H + (size_t)(r0 + 8*m2) * DIM + c) = hh;
                    *(__half2*)(L + (size_t)(r0 + 8*m2) * DIM + c) = ll;
                }
            }
        }
    } else {
#pragma unroll
        for (int ma = 0; ma < 4; ma++) {
            const int r0 = bm + wm * 64 + ma * 16 + g;
#pragma unroll
            for (int na = 0; na < 4; na++) {
                const int c = bn + wn * 32 + na * 8 + tig * 2;
                *(float2*)(Cf + (size_t)r0 * DIM + c)       = make_float2(acc[ma][na][0], acc[ma][na][1]);
                *(float2*)(Cf + (size_t)(r0 + 8) * DIM + c) = make_float2(acc[ma][na][2], acc[ma][na][3]);
            }
        }
    }
}

// ================= feature map via HMMA (3-product fp16 split) =================
#define FSTR 72    // fp16 row stride (144 B)

__global__ __launch_bounds__(128) void feature_mma(
    const __half* __restrict__ qh, const __half* __restrict__ ql,
    const __half* __restrict__ kh, const __half* __restrict__ kl,
    const __half* __restrict__ ph, const __half* __restrict__ pl,
    float* __restrict__ phiq, float* __restrict__ phik)
{
    __shared__ __half Ah[64*FSTR], Al[64*FSTR], Bh[64*FSTR], Bl[64*FSTR];
    __shared__ float sqs[64];
    const int t = threadIdx.x;
    const int lane = t & 31, wr = t >> 5;
    const int nb = ROWS / 64;
    const int isq = (blockIdx.x < nb) ? 1 : 0;
    const int blk = isq ? blockIdx.x : blockIdx.x - nb;
    const __half* Xh = isq ? qh : kh;
    const __half* Xl = isq ? ql : kl;
    float* phi = isq ? phiq : phik;
    const size_t base = (size_t)blk * 4096;

    for (int i = t; i < 512; i += 128) {
        int r = i >> 3, ch = i & 7;
        *(float4*)&Ah[r*FSTR + ch*8] = *(const float4*)(Xh + base + r*64 + ch*8);
        *(float4*)&Al[r*FSTR + ch*8] = *(const float4*)(Xl + base + r*64 + ch*8);
        *(float4*)&Bh[r*FSTR + ch*8] = *(const float4*)(ph + r*64 + ch*8);
        *(float4*)&Bl[r*FSTR + ch*8] = *(const float4*)(pl + r*64 + ch*8);
    }
    __syncthreads();

    // ||q||^2 per row (fp32 from hi+lo); rows t>>1, halves (t&1)*32
    {
        const int row = t >> 1, h0 = (t & 1) * 32;
        float s = 0.f;
#pragma unroll 8
        for (int d = 0; d < 32; d += 2) {
            __half2 a = *(__half2*)&Ah[row*FSTR + h0 + d];
            __half2 b = *(__half2*)&Al[row*FSTR + h0 + d];
            float q0 = __half2float(a.x) + __half2float(b.x);
            float q1 = __half2float(a.y) + __half2float(b.y);
            s += q0*q0 + q1*q1;
        }
        s += __shfl_xor_sync(0xffffffffu, s, 1);
        if (!(t & 1)) sqs[row] = s;
        __syncwarp();
    }

    // MMA: logits[64 rows x 64 f] = (Ah+Al) @ (Bh+Bl)^T, drop lo*lo
    float acc[8][4];
#pragma unroll
    for (int i = 0; i < 8; i++)
#pragma unroll
        for (int j = 0; j < 4; j++) acc[i][j] = 0.f;

    const uint32_t As = smem_u32(Ah), Als = smem_u32(Al);
    const uint32_t Bs = smem_u32(Bh), Bls = smem_u32(Bl);
    const int lrA = lane & 15, kbA = lane >> 4;
    const int nrB = (lane & 7) + ((lane >> 4) << 3);
    const int kbB = (lane >> 3) & 1;
#pragma unroll
    for (int ks = 0; ks < 4; ks++) {
        uint32_t ah[4], al[4];
        const uint32_t aoff = (uint32_t)((wr*16 + lrA) * (FSTR*2) + ks*32 + kbA*16);
        ldm_x4(ah, As + aoff);
        ldm_x4(al, Als + aoff);
#pragma unroll
        for (int nt2 = 0; nt2 < 4; nt2++) {
            const uint32_t boff = (uint32_t)((nt2*16 + nrB) * (FSTR*2) + ks*32 + kbB*16);
            uint32_t bh4[4], bl4[4];
            ldm_x4(bh4, Bs + boff);
            ldm_x4(bl4, Bls + boff);
            uint32_t b0h[2] = {bh4[0], bh4[1]}, b1h[2] = {bh4[2], bh4[3]};
            uint32_t b0l[2] = {bl4[0], bl4[1]}, b1l[2] = {bl4[2], bl4[3]};
            mma_f16(acc[2*nt2],   ah, b0h);
            mma_f16(acc[2*nt2],   ah, b0l);
            mma_f16(acc[2*nt2],   al, b0h);
            mma_f16(acc[2*nt2+1], ah, b1h);
            mma_f16(acc[2*nt2+1], ah, b1l);
            mma_f16(acc[2*nt2+1], al, b1h);
        }
    }

    // epilogue: rows wr*16 + g (+8); cols nt*8 + q*2
    const int g = lane >> 2, q = lane & 3;
#pragma unroll
    for (int half = 0; half < 2; half++) {
        const int row = wr*16 + g + half*8;
        float v[8][2];
#pragma unroll
        for (int nt = 0; nt < 8; nt++) {
            v[nt][0] = acc[nt][2*half];
            v[nt][1] = acc[nt][2*half + 1];
        }
        float sub = sqs[row] * (1.0f / 128.0f);
        if (isq) {
            float mx = v[0][0];
#pragma unroll
            for (int nt = 0; nt < 8; nt++) { mx = fmaxf(mx, v[nt][0]); mx = fmaxf(mx, v[nt][1]); }
            mx = fmaxf(mx, __shfl_xor_sync(0xffffffffu, mx, 1));
            mx = fmaxf(mx, __shfl_xor_sync(0xffffffffu, mx, 2));
            sub += mx;
        }
        float* dst = phi + base + (size_t)row * 64;
#pragma unroll
        for (int nt = 0; nt < 8; nt++) {
            float2 o;
            o.x = 0.125f * (__expf(v[nt][0] - sub) + 1e-4f);
            o.y = 0.125f * (__expf(v[nt][1] - sub) + 1e-4f);
            *(float2*)(dst + nt*8 + q*2) = o;
        }
    }
}

// ================= chunk_local =================
__global__ __launch_bounds__(256) void chunk_local_kernel(const float* __restrict__ phiK,
                                                          const float* __restrict__ V,
                                                          float* __restrict__ kvloc,
                                                          float* __restrict__ kloc)
{
    __shared__ float ks[64*PAD];
    __shared__ float vs[64*PAD];
    const int t = threadIdx.x;
    const int chunk = blockIdx.x, bh = blockIdx.y;
    const size_t base = ((size_t)bh * SEQ + chunk * CH) * 64;

    for (int i = t; i < 1024; i += 256) {
        int r = i >> 4, c4 = (i & 15) << 2;
        *(float4*)&ks[r*PAD + c4] = *(const float4*)(phiK + base + (size_t)r*64 + c4);
        *(float4*)&vs[r*PAD + c4] = *(const float4*)(V    + base + (size_t)r*64 + c4);
    }
    __syncthreads();

    const int f0 = (t >> 4) << 2;
    const int c0 = (t & 15) << 2;
    float acc[4][4], kl[4];
#pragma unroll
    for (int i = 0; i < 4; i++) { kl[i] = 0.f;
#pragma unroll
        for (int j = 0; j < 4; j++) acc[i][j] = 0.f; }

#pragma unroll 8
    for (int r = 0; r < 64; r++) {
        float4 k4 = *(const float4*)&ks[r*PAD + f0];
        float4 v4 = *(const float4*)&vs[r*PAD + c0];
        float kv[4] = {k4.x, k4.y, k4.z, k4.w};
        float vv[4] = {v4.x, v4.y, v4.z, v4.w};
#pragma unroll
        for (int i = 0; i < 4; i++) {
            kl[i] += kv[i];
#pragma unroll
            for (int j = 0; j < 4; j++) acc[i][j] += kv[i] * vv[j];
        }
    }
    const size_t ob = ((size_t)bh * NCHUNK + chunk) * (64*64);
#pragma unroll
    for (int i = 0; i < 4; i++)
        *(float4*)&kvloc[ob + (size_t)(f0+i)*64 + c0] =
            make_float4(acc[i][0], acc[i][1], acc[i][2], acc[i][3]);
    if ((t & 15) == 0) {
        const size_t kb = ((size_t)bh * NCHUNK + chunk) * 64 + f0;
#pragma unroll
        for (int i = 0; i < 4; i++) kloc[kb + i] = kl[i];
    }
}

// ================= prefix =================
__global__ __launch_bounds__(256) void prefix_kernel(float* __restrict__ kvloc,
                                                     float* __restrict__ kloc)
{
    const int g = blockIdx.x, bh = blockIdx.y;
    const int t = threadIdx.x;
    const int e = g * 256 + t;
    float run = 0.f;
    for (int c = 0; c < NCHUNK; c++) {
        const size_t idx = ((size_t)bh * NCHUNK + c) * 4096 + e;
        float v = kvloc[idx];
        kvloc[idx] = run;
        run += v;
    }
    if (g == 0 && t < 64) {
        float rk = 0.f;
        for (int c = 0; c < NCHUNK; c++) {
            const size_t b = ((size_t)bh * NCHUNK + c) * 64 + t;
            float v = kloc[b];
            kloc[b] = rk;
            rk += v;
        }
    }
}

// ================= chunk_out (single fp16 G output) =================
__global__ __launch_bounds__(256) void chunk_out_kernel(const float* __restrict__ phiQ,
                                                        const float* __restrict__ phiK,
                                                        const float* __restrict__ Vg,
                                                        const float* __restrict__ KVp,
                                                        const float* __restrict__ Kp,
                                                        __half* __restrict__ ahi)
{
    extern __shared__ float sm[];
    float* QsT = sm;
    float* KsT = QsT + 64*PAD;
    float* Vs  = KsT + 64*PAD;
    float* KVs = Vs  + 64*PAD;
    float* Ss  = KVs + 64*PAD;
    float* den = Ss  + 64*PAD;
    float* kps = den + 64;

    const int t = threadIdx.x;
    const int chunk = blockIdx.x, bh = blockIdx.y;
    const size_t base   = ((size_t)bh * SEQ + chunk * CH) * 64;
    const size_t kvbase = ((size_t)bh * NCHUNK + chunk) * 4096;

    for (int i = t; i < 1024; i += 256) {
        int r = i >> 4, c4 = (i & 15) << 2;
        float4 q = *(const float4*)(phiQ + base + (size_t)r*64 + c4);
        float4 k = *(const float4*)(phiK + base + (size_t)r*64 + c4);
        QsT[(c4+0)*PAD + r] = q.x; QsT[(c4+1)*PAD + r] = q.y;
        QsT[(c4+2)*PAD + r] = q.z; QsT[(c4+3)*PAD + r] = q.w;
        KsT[(c4+0)*PAD + r] = k.x; KsT[(c4+1)*PAD + r] = k.y;
        KsT[(c4+2)*PAD + r] = k.z; KsT[(c4+3)*PAD + r] = k.w;
        *(float4*)&Vs [r*PAD + c4] = *(const float4*)(Vg  + base   + (size_t)r*64 + c4);
        *(float4*)&KVs[r*PAD + c4] = *(const float4*)(KVp + kvbase + (size_t)r*64 + c4);
    }
    if (t < 64) kps[t] = Kp[((size_t)bh * NCHUNK + chunk) * 64 + t];
    __syncthreads();

    const int r0 = (t >> 4) << 2;
    const int c0 = (t & 15) << 2;

    // ---- Phase S ----
    float sacc[4][4], kq[4];
#pragma unroll
    for (int i = 0; i < 4; i++) { kq[i] = 0.f;
#pragma unroll
        for (int j = 0; j < 4; j++) sacc[i][j] = 0.f; }
#pragma unroll 8
    for (int d = 0; d < 64; d++) {
        float4 q4 = *(const float4*)&QsT[d*PAD + r0];
        float4 k4 = *(const float4*)&KsT[d*PAD + c0];
        float kp = kps[d];
        float qv[4] = {q4.x, q4.y, q4.z, q4.w};
        float kv[4] = {k4.x, k4.y, k4.z, k4.w};
#pragma unroll
        for (int i = 0; i < 4; i++) {
            kq[i] += qv[i] * kp;
#pragma unroll
            for (int j = 0; j < 4; j++) sacc[i][j] += qv[i] * kv[j];
        }
    }
    float rs[4];
#pragma unroll
    for (int i = 0; i < 4; i++) {
        const int r = r0 + i;
        float m0 = (c0+0 <= r) ? sacc[i][0] : 0.f;
        float m1 = (c0+1 <= r) ? sacc[i][1] : 0.f;
        float m2 = (c0+2 <= r) ? sacc[i][2] : 0.f;
        float m3 = (c0+3 <= r) ? sacc[i][3] : 0.f;
        *(float4*)&Ss[r*PAD + c0] = make_float4(m0, m1, m2, m3);
        rs[i] = m0 + m1 + m2 + m3;
    }
#pragma unroll
    for (int o = 8; o >= 1; o >>= 1)
#pragma unroll
        for (int i = 0; i < 4; i++) rs[i] += __shfl_xor_sync(0xffffffffu, rs[i], o);
    if ((t & 15) == 0) {
#pragma unroll
        for (int i = 0; i < 4; i++) den[r0 + i] = fmaxf(rs[i] + kq[i], 1e-6f);
    }
    __syncthreads();

    // ---- Phase O: G = (S V + Q KVprev) / den ----
    float oacc[4][4];
#pragma unroll
    for (int i = 0; i < 4; i++)
#pragma unroll
        for (int j = 0; j < 4; j++) oacc[i][j] = 0.f;
#pragma unroll 4
    for (int j0 = 0; j0 < 64; j0 += 4) {
        float4 s4[4], v4[4];
#pragma unroll
        for (int i = 0; i < 4; i++)  s4[i]  = *(const float4*)&Ss[(r0+i)*PAD + j0];
#pragma unroll
        for (int jj = 0; jj < 4; jj++) v4[jj] = *(const float4*)&Vs[(j0+jj)*PAD + c0];
#pragma unroll
        for (int i = 0; i < 4; i++) {
            float sv[4] = {s4[i].x, s4[i].y, s4[i].z, s4[i].w};
#pragma unroll
            for (int jj = 0; jj < 4; jj++) {
                oacc[i][0] += sv[jj] * (&v4[jj].x)[0];
                oacc[i][1] += sv[jj] * (&v4[jj].x)[1];
                oacc[i][2] += sv[jj] * (&v4[jj].x)[2];
                oacc[i][3] += sv[jj] * (&v4[jj].x)[3];
            }
        }
    }
#pragma unroll 4
    for (int f0 = 0; f0 < 64; f0 += 4) {
        float4 q4[4], kv4[4];
#pragma unroll
        for (int jj = 0; jj < 4; jj++) {
            q4[jj]  = *(const float4*)&QsT[(f0+jj)*PAD + r0];
            kv4[jj] = *(const float4*)&KVs[(f0+jj)*PAD + c0];
        }
#pragma unroll
        for (int jj = 0; jj < 4; jj++) {
            float qv[4] = {q4[jj].x, q4[jj].y, q4[jj].z, q4[jj].w};
#pragma unroll
            for (int i = 0; i < 4; i++) {
                oacc[i][0] += qv[i] * (&kv4[jj].x)[0];
                oacc[i][1] += qv[i] * (&kv4[jj].x)[1];
                oacc[i][2] += qv[i] * (&kv4[jj].x)[2];
                oacc[i][3] += qv[i] * (&kv4[jj].x)[3];
            }
        }
    }

    // ---- store G with head-transpose (single fp16) ----
    const int bi = bh >> 4, hi2 = bh & 15;
#pragma unroll
    for (int i = 0; i < 4; i++) {
        const float inv = 1.0f / den[r0 + i];
        const int si = chunk * CH + r0 + i;
        const size_t ob = ((size_t)bi * SEQ + si) * DIM + hi2 * 64 + c0;
        __half2 hp[2];
#pragma unroll
        for (int j = 0; j < 2; j++) {
            hp[j].x = __float2half(oacc[i][2*j] * inv);
            hp[j].y = __float2half(oacc[i][2*j+1] * inv);
        }
        *(float2*)(ahi + ob) = *(float2*)hp;
    }
}

// ================= launch =================
extern "C" void kernel_launch(void* const* d_in, const int* in_sizes, int n_in,
                              void* d_out, int out_size)
{
    const float* x     = (const float*)d_in[0];
    const float* Wq    = (const float*)d_in[1];
    const float* Wk    = (const float*)d_in[2];
    const float* Wv    = (const float*)d_in[3];
    const float* proj  = (const float*)d_in[4];
    const float* Wpost = (const float*)d_in[5];
    const float* Wout  = (const float*)d_in[6];
    float* out = (float*)d_out;

    float *pV, *pphiq, *pphik, *pkv, *pks;
    __half *pxhi, *pxlo, *pahi, *pwh, *pqhi, *pqlo, *pkhi, *pklo, *pph, *ppl;
    cudaGetSymbolAddress((void**)&pV, g_V);
    cudaGetSymbolAddress((void**)&pphiq, g_phiq);
    cudaGetSymbolAddress((void**)&pphik, g_phik);
    cudaGetSymbolAddress((void**)&pkv, g_kv);
    cudaGetSymbolAddress((void**)&pks, g_ks);
    cudaGetSymbolAddress((void**)&pxhi, g_xhi);
    cudaGetSymbolAddress((void**)&pxlo, g_xlo);
    cudaGetSymbolAddress((void**)&pahi, g_ahi);
    cudaGetSymbolAddress((void**)&pwh, g_wh);
    cudaGetSymbolAddress((void**)&pqhi, g_qhi);
    cudaGetSymbolAddress((void**)&pqlo, g_qlo);
    cudaGetSymbolAddress((void**)&pkhi, g_khi);
    cudaGetSymbolAddress((void**)&pklo, g_klo);
    cudaGetSymbolAddress((void**)&pph, g_ph);
    cudaGetSymbolAddress((void**)&ppl, g_pl);

    static const size_t chunk_smem = (size_t)(5*64*PAD + 128) * sizeof(float);
    cudaFuncSetAttribute(chunk_out_kernel, cudaFuncAttributeMaxDynamicSharedMemorySize,
                         (int)chunk_smem);
    static const int gemm_smem = NSTAGE * BUFB;     // 92160 B
    cudaFuncSetAttribute(gemm_hmma_split, cudaFuncAttributeMaxDynamicSharedMemorySize, gemm_smem);

    convert_all<<<11268, 256>>>(x, Wq, Wk, Wv, proj, pxhi, pxlo, pwh, pph, ppl);
    w2_kernel<<<dim3(16, 16), 256>>>(Wout, Wpost, pwh + 3*DIM*DIM);

    dim3 gqkv(24, MROWS/128);
    gemm_hmma_split<<<gqkv, 256, gemm_smem>>>(pxhi, pxlo, pwh,
                                              pqhi, pqlo, pkhi, pklo, pV, 0, 2, DIM);

    feature_mma<<<2*(ROWS/64), 128>>>(pqhi, pqlo, pkhi, pklo, pph, ppl, pphiq, pphik);

    dim3 gc(NCHUNK, NBH);
    chunk_local_kernel<<<gc, 256>>>(pphik, pV, pkv, pks);
    dim3 gp(16, NBH);
    prefix_kernel<<<gp, 256>>>(pkv, pks);
    chunk_out_kernel<<<gc, 256, chunk_smem>>>(pphiq, pphik, pV, pkv, pks, pahi);

    // final projection: single A product (G fp16), B = W2
    dim3 gout(8, MROWS/128);
    gemm_hmma_split<<<gout, 256, gemm_smem>>>(pahi, pahi, pwh + 3*DIM*DIM,
                                              (__half*)0, (__half*)0, (__half*)0, (__half*)0,
                                              out, 1, 1, DIM);
}